// round 11
// baseline (speedup 1.0000x reference)
#include <cuda_runtime.h>
#include <cuda_fp16.h>

#define BB 2
#define LL 384
#define HH 8
#define DD 64
#define HIDN 512
#define BH (BB*HH)          // 16
#define MROWS (BB*LL)       // 768
#define X_ELEMS (MROWS*HIDN)    // 393216
#define A_ELEMS (BH*LL*LL)      // 2359296
#define FD 256              // feature dim (4 segments x 64)

// -------- scratch (no dynamic allocation allowed) --------
__device__ __half g_FQ[BH*LL*FD];   // [bh][l][256]  q-side features
__device__ __half g_FK[BH*LL*FD];   // [bh][l][256]  k-side features
__device__ __half g_Vh[BH*DD*LL];   // [bh][d][l]    V transposed, half
__device__ float  g_ck[BH*LL];      // per-k energy constant
__device__ float  g_X [X_ELEMS];
__device__ float  g_attn[A_ELEMS];
__device__ float  g_Wfq[HIDN*HIDN];
__device__ float  g_Wfk[HIDN*HIDN];
__device__ float  g_bfq[HIDN];
__device__ float  g_bfk[HIDN];

__device__ __forceinline__ float tanh_ap(float x) {
    float y; asm("tanh.approx.f32 %0, %1;" : "=f"(y) : "f"(x)); return y;
}
__device__ __forceinline__ unsigned f2tf32(float f) {
    unsigned u; asm("cvt.rna.tf32.f32 %0, %1;" : "=r"(u) : "f"(f)); return u;
}
__device__ __forceinline__ void mma_tf32(float* c, const unsigned* a, const unsigned* b) {
    asm volatile(
        "mma.sync.aligned.m16n8k8.row.col.f32.tf32.tf32.f32 "
        "{%0,%1,%2,%3}, {%4,%5,%6,%7}, {%8,%9}, {%0,%1,%2,%3};"
        : "+f"(c[0]), "+f"(c[1]), "+f"(c[2]), "+f"(c[3])
        : "r"(a[0]), "r"(a[1]), "r"(a[2]), "r"(a[3]), "r"(b[0]), "r"(b[1]));
}
__device__ __forceinline__ void mma_f16(float* c, const unsigned* a, const unsigned* b) {
    asm volatile(
        "mma.sync.aligned.m16n8k16.row.col.f32.f16.f16.f32 "
        "{%0,%1,%2,%3}, {%4,%5,%6,%7}, {%8,%9}, {%0,%1,%2,%3};"
        : "+f"(c[0]), "+f"(c[1]), "+f"(c[2]), "+f"(c[3])
        : "r"(a[0]), "r"(a[1]), "r"(a[2]), "r"(a[3]), "r"(b[0]), "r"(b[1]));
}
__device__ __forceinline__ unsigned h2u(__half2 v) { return *(unsigned*)&v; }
__device__ __forceinline__ void cpa16(void* smem, const void* g) {
    unsigned s = (unsigned)__cvta_generic_to_shared(smem);
    asm volatile("cp.async.ca.shared.global [%0], [%1], 16;" :: "r"(s), "l"(g));
}

// ---------------- prep: fused per-head weights ----------------
__global__ void __launch_bounds__(256) prep_fuse(
    const float* __restrict__ W1, const float* __restrict__ b1,
    const float* __restrict__ W2, const float* __restrict__ b2,
    const float* __restrict__ Wq, const float* __restrict__ bq,
    const float* __restrict__ Wk, const float* __restrict__ bk)
{
    int h   = blockIdx.x;
    int sel = blockIdx.y;
    int c0  = blockIdx.z * 64;
    const float* Wh   = sel ? W2 : W1;
    const float* bh_  = sel ? b2 : b1;
    const float* Wsrc = sel ? Wk : Wq;
    const float* bsrc = sel ? bk : bq;
    float* Wout = sel ? g_Wfk : g_Wfq;
    float* bout = sel ? g_bfk : g_bfq;
    __shared__ float Ws[DD][DD + 1];
    __shared__ float Ts[DD][DD + 1];
    int tid = threadIdx.x;
    for (int t = tid; t < DD * DD; t += 256) {
        Ws[t >> 6][t & 63] = Wh[t];
        Ts[t >> 6][t & 63] = Wsrc[(h * DD + (t >> 6)) * HIDN + c0 + (t & 63)];
    }
    __syncthreads();
    if (blockIdx.z == 0 && tid < DD) {
        float acc = bh_[tid];
        for (int j = 0; j < DD; j++) acc += Ws[tid][j] * bsrc[h * DD + j];
        bout[h * DD + tid] = acc;
    }
    int i = tid & 63;
    int g = tid >> 6;
#pragma unroll
    for (int cc = 0; cc < 16; cc++) {
        int c = g * 16 + cc;
        float acc = 0.f;
#pragma unroll 8
        for (int j = 0; j < DD; j++) acc = fmaf(Ws[i][j], Ts[j][c], acc);
        Wout[(h * DD + i) * HIDN + c0 + c] = acc;
    }
}

// ---------------- tf32 TC GEMM v3b: cp.async 3-stage pipeline + RN cvt at frag load ----
// mode 0: plain fp32 [m, HIDN]; mode 3: Q-featurize; mode 4: K-featurize+ck; mode 5: V->half [d][l]
#define GST 40                   // stage row stride in floats (16B-aligned rows)
#define GSTAGE (64*GST)          // floats per array per stage
#define SMEM_G (3*2*GSTAGE*4)    // 61440 B

__global__ void __launch_bounds__(256) gemm_tc(
    const float* __restrict__ X0, const float* __restrict__ Wm0, const float* __restrict__ B0, float* __restrict__ O0, int md0,
    const float* __restrict__ X1, const float* __restrict__ Wm1, const float* __restrict__ B1, float* __restrict__ O1, int md1,
    const float* __restrict__ X2, const float* __restrict__ Wm2, const float* __restrict__ B2, float* __restrict__ O2, int md2,
    const float* __restrict__ vw)
{
    const int BK = 32, NIT = HIDN / BK;   // 16
    int z = blockIdx.z;
    const float* X  = z == 0 ? X0  : (z == 1 ? X1  : X2);
    const float* W  = z == 0 ? Wm0 : (z == 1 ? Wm1 : Wm2);
    const float* Bi = z == 0 ? B0  : (z == 1 ? B1  : B2);
    float*       O  = z == 0 ? O0  : (z == 1 ? O1  : O2);
    int        mode = z == 0 ? md0 : (z == 1 ? md1 : md2);

    extern __shared__ float smg[];
    float* outT = smg;               // epilogue overlay [64][68]

    int tid = threadIdx.x;
    int lane = tid & 31;
    int warp = tid >> 5;
    int warp_m = (warp & 3) * 16;
    int warp_n = (warp >> 2) * 32;
    int gr = lane >> 2;
    int tg = lane & 3;
    int m0 = blockIdx.y * 64, n0 = blockIdx.x * 64;

    int ldr  = tid >> 3;             // 0..31
    int ldc4 = tid & 7;              // 0..7

    float acc[4][4];
#pragma unroll
    for (int nt = 0; nt < 4; nt++)
#pragma unroll
        for (int i = 0; i < 4; i++) acc[nt][i] = 0.f;

    auto issue = [&](int buf, int kk) {
        float* sX = smg + buf * 2 * GSTAGE;
        float* sW = sX + GSTAGE;
#pragma unroll
        for (int i = 0; i < 2; i++) {
            int r = ldr + i * 32;
            cpa16(&sX[r * GST + ldc4 * 4], &X[(m0 + r) * HIDN + kk + ldc4 * 4]);
            cpa16(&sW[r * GST + ldc4 * 4], &W[(n0 + r) * HIDN + kk + ldc4 * 4]);
        }
    };

    issue(0, 0);
    asm volatile("cp.async.commit_group;");
    issue(1, BK);
    asm volatile("cp.async.commit_group;");

    for (int it = 0; it < NIT; it++) {
        asm volatile("cp.async.wait_group 1;");
        __syncthreads();
        if (it + 2 < NIT) issue((it + 2) % 3, (it + 2) * BK);
        asm volatile("cp.async.commit_group;");

        const float* sX = smg + (it % 3) * 2 * GSTAGE;
        const float* sW = sX + GSTAGE;
#pragma unroll
        for (int k8 = 0; k8 < 4; k8++) {
            int kb = k8 * 8;
            unsigned a[4], b[4][2];
            // RN conversion in registers (matches R9 numerics)
            a[0] = f2tf32(sX[(warp_m + gr    ) * GST + kb + tg]);
            a[1] = f2tf32(sX[(warp_m + gr + 8) * GST + kb + tg]);
            a[2] = f2tf32(sX[(warp_m + gr    ) * GST + kb + tg + 4]);
            a[3] = f2tf32(sX[(warp_m + gr + 8) * GST + kb + tg + 4]);
#pragma unroll
            for (int nt = 0; nt < 4; nt++) {
                int rn = warp_n + nt * 8 + gr;
                b[nt][0] = f2tf32(sW[rn * GST + kb + tg]);
                b[nt][1] = f2tf32(sW[rn * GST + kb + tg + 4]);
            }
#pragma unroll
            for (int nt = 0; nt < 4; nt++)
                mma_tf32(acc[nt], a, b[nt]);
        }
        __syncthreads();
    }

    // epilogue: acc -> smem tile (overlays stage buffers)
#pragma unroll
    for (int nt = 0; nt < 4; nt++) {
        int col = warp_n + nt * 8 + 2 * tg;
        outT[(warp_m + gr    ) * 68 + col    ] = acc[nt][0];
        outT[(warp_m + gr    ) * 68 + col + 1] = acc[nt][1];
        outT[(warp_m + gr + 8) * 68 + col    ] = acc[nt][2];
        outT[(warp_m + gr + 8) * 68 + col + 1] = acc[nt][3];
    }
    __syncthreads();

    int b_ = m0 / LL, l0 = m0 - b_ * LL;
    int h = n0 >> 6;
    int bh = b_ * HH + h;

    if (mode == 0) {
#pragma unroll
        for (int i = 0; i < 4; i++) {
            int idx = tid + i * 256;
            int r = idx >> 4, c4 = idx & 15;
            float4 v = *(float4*)&outT[r * 68 + c4 * 4];
            float4 b4 = *(const float4*)&Bi[n0 + c4 * 4];
            v.x += b4.x; v.y += b4.y; v.z += b4.z; v.w += b4.w;
            *(float4*)&O[(m0 + r) * HIDN + n0 + c4 * 4] = v;
        }
    } else if (mode == 3 || mode == 4) {
        __half* Fdst = (mode == 3 ? g_FQ : g_FK) + (size_t)(bh * LL + l0) * FD;
#pragma unroll
        for (int i = 0; i < 4; i++) {
            int idx = tid + i * 256;
            int r = idx >> 4, c4 = idx & 15;
            int d0 = c4 * 4;
            float4 v = *(float4*)&outT[r * 68 + d0];
            float4 b4 = *(const float4*)&Bi[n0 + d0];
            float t0 = tanh_ap(v.x + b4.x), t1 = tanh_ap(v.y + b4.y);
            float t2 = tanh_ap(v.z + b4.z), t3 = tanh_ap(v.w + b4.w);
            float w0 = __ldg(&vw[d0]), w1 = __ldg(&vw[d0 + 1]);
            float w2 = __ldg(&vw[d0 + 2]), w3 = __ldg(&vw[d0 + 3]);
            __half* row = Fdst + (size_t)r * FD;
            if (mode == 3) {
                // FQ = [ta^2, vw*ta, ta^3, vw*ta^2]
                *(__half2*)&row[0*64 + d0    ] = __floats2half2_rn(t0*t0, t1*t1);
                *(__half2*)&row[0*64 + d0 + 2] = __floats2half2_rn(t2*t2, t3*t3);
                *(__half2*)&row[1*64 + d0    ] = __floats2half2_rn(w0*t0, w1*t1);
                *(__half2*)&row[1*64 + d0 + 2] = __floats2half2_rn(w2*t2, w3*t3);
                *(__half2*)&row[2*64 + d0    ] = __floats2half2_rn(t0*t0*t0, t1*t1*t1);
                *(__half2*)&row[2*64 + d0 + 2] = __floats2half2_rn(t2*t2*t2, t3*t3*t3);
                *(__half2*)&row[3*64 + d0    ] = __floats2half2_rn(w0*t0*t0, w1*t1*t1);
                *(__half2*)&row[3*64 + d0 + 2] = __floats2half2_rn(w2*t2*t2, w3*t3*t3);
            } else {
                // FK = [-vw*tb, -tb^2, vw*tb^2, tb^3]
                *(__half2*)&row[0*64 + d0    ] = __floats2half2_rn(-w0*t0, -w1*t1);
                *(__half2*)&row[0*64 + d0 + 2] = __floats2half2_rn(-w2*t2, -w3*t3);
                *(__half2*)&row[1*64 + d0    ] = __floats2half2_rn(-t0*t0, -t1*t1);
                *(__half2*)&row[1*64 + d0 + 2] = __floats2half2_rn(-t2*t2, -t3*t3);
                *(__half2*)&row[2*64 + d0    ] = __floats2half2_rn(w0*t0*t0, w1*t1*t1);
                *(__half2*)&row[2*64 + d0 + 2] = __floats2half2_rn(w2*t2*t2, w3*t3*t3);
                *(__half2*)&row[3*64 + d0    ] = __floats2half2_rn(t0*t0*t0, t1*t1*t1);
                *(__half2*)&row[3*64 + d0 + 2] = __floats2half2_rn(t2*t2*t2, t3*t3*t3);
                float cp = w0*t0 + w1*t1 + w2*t2 + w3*t3;
#pragma unroll
                for (int o = 1; o < 16; o <<= 1) cp += __shfl_xor_sync(0xffffffffu, cp, o);
                if ((tid & 15) == 0) g_ck[bh * LL + l0 + r] = cp;
            }
        }
    } else {
        // mode 5: V -> half, transposed [bh][d][l]
        __half* base = g_Vh + (size_t)bh * DD * LL;
#pragma unroll
        for (int i = 0; i < 4; i++) {
            int idx = tid + i * 256;
            int d = idx >> 4, l4 = idx & 15;
            float bd = __ldg(&Bi[n0 + d]);
            float v0 = outT[(l4 * 4 + 0) * 68 + d] + bd;
            float v1 = outT[(l4 * 4 + 1) * 68 + d] + bd;
            float v2 = outT[(l4 * 4 + 2) * 68 + d] + bd;
            float v3 = outT[(l4 * 4 + 3) * 68 + d] + bd;
            *(__half2*)&base[d * LL + l0 + l4 * 4    ] = __floats2half2_rn(v0, v1);
            *(__half2*)&base[d * LL + l0 + l4 * 4 + 2] = __floats2half2_rn(v2, v3);
        }
    }
}

// ---------------- attention: E = FQ@FK^T + ck -> softmax -> X = P@V (f16 MMA) ----
#define LLP 392
#define FDP 264
#define VHS 72
#define EOFF  0
#define UOFF  (32*LLP*4)                       // 50176
#define FQOFF UOFF
#define FKOFF (UOFF + 32*FDP*2)                // +16896
#define VHOFF UOFF
#define CKOFF (UOFF + 32*FDP*2 + 64*FDP*2)     // 100864
#define MOFF  (CKOFF + LL*4)                   // 102400
#define SMEM_ATTN (MOFF + LL*4)                // 103936

__global__ void __launch_bounds__(256) attn_fused(
    const int* __restrict__ mask, float* __restrict__ attn)
{
    extern __shared__ char smraw[];
    float*  E  = (float*) (smraw + EOFF);   // [32][LLP]
    __half* FQ = (__half*)(smraw + FQOFF);  // [32][FDP]
    __half* FK = (__half*)(smraw + FKOFF);  // [64][FDP]
    __half* Vh = (__half*)(smraw + VHOFF);  // [64][VHS]
    float*  CK = (float*) (smraw + CKOFF);
    int*    M  = (int*)   (smraw + MOFF);

    int tid = threadIdx.x;
    int lane = tid & 31, warp = tid >> 5;
    int wm = (warp & 1) * 16;
    int wn = (warp >> 1) * 16;
    int gr = lane >> 2, tg = lane & 3;
    int bh = blockIdx.y, b = bh >> 3, h = bh & 7;
    int q0 = blockIdx.x * 32;

    for (int j = tid; j < LL; j += 256) { M[j] = mask[b * LL + j]; CK[j] = g_ck[bh * LL + j]; }
    {
        const unsigned* s32 = (const unsigned*)(g_FQ + (size_t)(bh * LL + q0) * FD);
#pragma unroll
        for (int i = 0; i < 16; i++) {
            int idx = tid + i * 256;
            int r = idx >> 7, c2 = idx & 127;
            *(unsigned*)&FQ[r * FDP + c2 * 2] = s32[r * 128 + c2];
        }
    }

    for (int c = 0; c < 6; c++) {
        __syncthreads();
        {
            const unsigned* s32 = (const unsigned*)(g_FK + (size_t)(bh * LL + c * 64) * FD);
#pragma unroll
            for (int i = 0; i < 32; i++) {
                int idx = tid + i * 256;
                int r = idx >> 7, c2 = idx & 127;
                *(unsigned*)&FK[r * FDP + c2 * 2] = s32[r * 128 + c2];
            }
        }
        __syncthreads();
        float eacc[2][4];
#pragma unroll
        for (int nt = 0; nt < 2; nt++)
#pragma unroll
            for (int i = 0; i < 4; i++) eacc[nt][i] = 0.f;
#pragma unroll
        for (int ks = 0; ks < 16; ks++) {
            int k0 = ks * 16;
            unsigned a[4], bf[2][2];
            a[0] = *(const unsigned*)&FQ[(wm + gr    ) * FDP + k0 + 2 * tg];
            a[1] = *(const unsigned*)&FQ[(wm + gr + 8) * FDP + k0 + 2 * tg];
            a[2] = *(const unsigned*)&FQ[(wm + gr    ) * FDP + k0 + 2 * tg + 8];
            a[3] = *(const unsigned*)&FQ[(wm + gr + 8) * FDP + k0 + 2 * tg + 8];
#pragma unroll
            for (int nt = 0; nt < 2; nt++) {
                int rn = wn + nt * 8 + gr;
                bf[nt][0] = *(const unsigned*)&FK[rn * FDP + k0 + 2 * tg];
                bf[nt][1] = *(const unsigned*)&FK[rn * FDP + k0 + 2 * tg + 8];
            }
            mma_f16(eacc[0], a, bf[0]);
            mma_f16(eacc[1], a, bf[1]);
        }
#pragma unroll
        for (int nt = 0; nt < 2; nt++) {
            int col = c * 64 + wn + nt * 8 + 2 * tg;
            *(float2*)&E[(wm + gr    ) * LLP + col] = make_float2(eacc[nt][0], eacc[nt][1]);
            *(float2*)&E[(wm + gr + 8) * LLP + col] = make_float2(eacc[nt][2], eacc[nt][3]);
        }
    }
    __syncthreads();

    {
        int row = tid >> 3, lx = tid & 7;
        float mx = -3.0e38f;
        for (int i = 0; i < 48; i++) {
            int j = lx + i * 8;
            float e = E[row * LLP + j] + CK[j];
            if (M[j] == 0) e = -1e10f;
            E[row * LLP + j] = e;
            mx = fmaxf(mx, e);
        }
#pragma unroll
        for (int o = 4; o > 0; o >>= 1) mx = fmaxf(mx, __shfl_xor_sync(0xffffffffu, mx, o));
        float sum = 0.f;
        for (int i = 0; i < 48; i++) {
            int j = lx + i * 8;
            float p = __expf(E[row * LLP + j] - mx);
            sum += p;
            E[row * LLP + j] = p;
        }
#pragma unroll
        for (int o = 4; o > 0; o >>= 1) sum += __shfl_xor_sync(0xffffffffu, sum, o);
        float inv = __frcp_rn(sum);
        for (int i = 0; i < 48; i++) E[row * LLP + lx + i * 8] *= inv;
    }
    __syncthreads();

    {
        float* dst = attn + (size_t)(bh * LL + q0) * LL;
        for (int idx = tid; idx < 32 * LL; idx += 256) {
            int r = idx / LL, j = idx - r * LL;
            dst[r * LL + j] = E[r * LLP + j];
        }
    }

    float xacc[2][4];
#pragma unroll
    for (int nt = 0; nt < 2; nt++)
#pragma unroll
        for (int i = 0; i < 4; i++) xacc[nt][i] = 0.f;

    for (int c = 0; c < 6; c++) {
        __syncthreads();
        {
            const unsigned* s32 = (const unsigned*)(g_Vh + (size_t)bh * DD * LL + c * 64);
#pragma unroll
            for (int i = 0; i < 8; i++) {
                int idx = tid + i * 256;
                int d = idx >> 5, c2 = idx & 31;
                *(unsigned*)&Vh[d * VHS + c2 * 2] = s32[d * (LL / 2) + c2];
            }
        }
        __syncthreads();
#pragma unroll
        for (int ks = 0; ks < 4; ks++) {
            int kg = c * 64 + ks * 16;
            unsigned a[4], bf[2][2];
            float2 p0 = *(const float2*)&E[(wm + gr    ) * LLP + kg + 2 * tg];
            float2 p1 = *(const float2*)&E[(wm + gr + 8) * LLP + kg + 2 * tg];
            float2 p2 = *(const float2*)&E[(wm + gr    ) * LLP + kg + 2 * tg + 8];
            float2 p3 = *(const float2*)&E[(wm + gr + 8) * LLP + kg + 2 * tg + 8];
            a[0] = h2u(__floats2half2_rn(p0.x, p0.y));
            a[1] = h2u(__floats2half2_rn(p1.x, p1.y));
            a[2] = h2u(__floats2half2_rn(p2.x, p2.y));
            a[3] = h2u(__floats2half2_rn(p3.x, p3.y));
            int kl = ks * 16 + 2 * tg;
#pragma unroll
            for (int nt = 0; nt < 2; nt++) {
                int rn = wn + nt * 8 + gr;
                bf[nt][0] = *(const unsigned*)&Vh[rn * VHS + kl];
                bf[nt][1] = *(const unsigned*)&Vh[rn * VHS + kl + 8];
            }
            mma_f16(xacc[0], a, bf[0]);
            mma_f16(xacc[1], a, bf[1]);
        }
    }

    {
        int q = q0 + wm + gr;
#pragma unroll
        for (int nt = 0; nt < 2; nt++) {
            int d = h * DD + wn + nt * 8 + 2 * tg;
            *(float2*)&g_X[(size_t)(b * LL + q    ) * HIDN + d] = make_float2(xacc[nt][0], xacc[nt][1]);
            *(float2*)&g_X[(size_t)(b * LL + q + 8) * HIDN + d] = make_float2(xacc[nt][2], xacc[nt][3]);
        }
    }
}

extern "C" void kernel_launch(void* const* d_in, const int* in_sizes, int n_in,
                              void* d_out, int out_size)
{
    const float* query = (const float*)d_in[0];
    const float* key_  = (const float*)d_in[1];
    const float* value = (const float*)d_in[2];
    const int*   mask  = (const int*)  d_in[3];
    const float* Wq = (const float*)d_in[4];
    const float* bq = (const float*)d_in[5];
    const float* Wk = (const float*)d_in[6];
    const float* bk = (const float*)d_in[7];
    const float* Wv = (const float*)d_in[8];
    const float* bv = (const float*)d_in[9];
    const float* Wo = (const float*)d_in[10];
    const float* bo = (const float*)d_in[11];
    const float* W1 = (const float*)d_in[12];
    const float* b1 = (const float*)d_in[13];
    const float* W2 = (const float*)d_in[14];
    const float* b2 = (const float*)d_in[15];
    const float* vw = (const float*)d_in[16];
    (void)d_in[17];
    (void)in_sizes; (void)n_in;

    float* out = (float*)d_out;

    float *gX, *gA, *gWfq, *gWfk, *gbfq, *gbfk;
    cudaGetSymbolAddress((void**)&gX,   g_X);
    cudaGetSymbolAddress((void**)&gA,   g_attn);
    cudaGetSymbolAddress((void**)&gWfq, g_Wfq);
    cudaGetSymbolAddress((void**)&gWfk, g_Wfk);
    cudaGetSymbolAddress((void**)&gbfq, g_bfq);
    cudaGetSymbolAddress((void**)&gbfk, g_bfk);

    float* attn_dst = (out_size >= X_ELEMS + A_ELEMS) ? (out + X_ELEMS) : gA;

    cudaFuncSetAttribute(gemm_tc, cudaFuncAttributeMaxDynamicSharedMemorySize, SMEM_G);
    cudaFuncSetAttribute(attn_fused, cudaFuncAttributeMaxDynamicSharedMemorySize, SMEM_ATTN);

    // 1) fuse W1@Wq and W2@Wk (128 blocks)
    prep_fuse<<<dim3(HH, 2, HIDN / 64), 256>>>(W1, b1, W2, b2, Wq, bq, Wk, bk);

    // 2) projections + featurization — cp.async tf32 TC, 288 blocks
    gemm_tc<<<dim3(HIDN / 64, MROWS / 64, 3), 256, SMEM_G>>>(
        query, gWfq, gbfq, nullptr, 3,
        key_,  gWfk, gbfk, nullptr, 4,
        value, Wv,   bv,   nullptr, 5,
        vw);

    // 3) attention: E-mma + softmax + AV-mma (192 blocks, dyn smem)
    attn_fused<<<dim3(LL / 32, BH), 256, SMEM_ATTN>>>(mask, attn_dst);

    // 4) output projection — cp.async tf32 TC (96 blocks)
    gemm_tc<<<dim3(HIDN / 64, MROWS / 64, 1), 256, SMEM_G>>>(
        gX, Wo, bo, out, 0,
        gX, Wo, bo, out, 0,
        gX, Wo, bo, out, 0,
        vw);
}

// round 12
// speedup vs baseline: 1.0806x; 1.0806x over previous
#include <cuda_runtime.h>
#include <cuda_fp16.h>

#define BB 2
#define LL 384
#define HH 8
#define DD 64
#define HIDN 512
#define BH (BB*HH)          // 16
#define MROWS (BB*LL)       // 768
#define X_ELEMS (MROWS*HIDN)    // 393216
#define A_ELEMS (BH*LL*LL)      // 2359296
#define FD 256              // feature dim (4 segments x 64)

// -------- scratch (no dynamic allocation allowed) --------
__device__ __half g_FQ[BH*LL*FD];   // [bh][l][256]  q-side features
__device__ __half g_FK[BH*LL*FD];   // [bh][l][256]  k-side features
__device__ __half g_Vh[BH*DD*LL];   // [bh][d][l]    V transposed, half
__device__ float  g_ck[BH*LL];      // per-k energy constant
__device__ float  g_X [X_ELEMS];
__device__ float  g_attn[A_ELEMS];
__device__ float  g_Wfq[HIDN*HIDN];
__device__ float  g_Wfk[HIDN*HIDN];
__device__ float  g_bfq[HIDN];
__device__ float  g_bfk[HIDN];

__device__ __forceinline__ float tanh_ap(float x) {
    float y; asm("tanh.approx.f32 %0, %1;" : "=f"(y) : "f"(x)); return y;
}
__device__ __forceinline__ unsigned f2tf32(float f) {
    unsigned u; asm("cvt.rna.tf32.f32 %0, %1;" : "=r"(u) : "f"(f)); return u;
}
__device__ __forceinline__ void mma_tf32(float* c, const unsigned* a, const unsigned* b) {
    asm volatile(
        "mma.sync.aligned.m16n8k8.row.col.f32.tf32.tf32.f32 "
        "{%0,%1,%2,%3}, {%4,%5,%6,%7}, {%8,%9}, {%0,%1,%2,%3};"
        : "+f"(c[0]), "+f"(c[1]), "+f"(c[2]), "+f"(c[3])
        : "r"(a[0]), "r"(a[1]), "r"(a[2]), "r"(a[3]), "r"(b[0]), "r"(b[1]));
}
__device__ __forceinline__ void mma_f16(float* c, const unsigned* a, const unsigned* b) {
    asm volatile(
        "mma.sync.aligned.m16n8k16.row.col.f32.f16.f16.f32 "
        "{%0,%1,%2,%3}, {%4,%5,%6,%7}, {%8,%9}, {%0,%1,%2,%3};"
        : "+f"(c[0]), "+f"(c[1]), "+f"(c[2]), "+f"(c[3])
        : "r"(a[0]), "r"(a[1]), "r"(a[2]), "r"(a[3]), "r"(b[0]), "r"(b[1]));
}
__device__ __forceinline__ unsigned h2u(__half2 v) { return *(unsigned*)&v; }

// ---------------- prep: fused per-head weights ----------------
__global__ void __launch_bounds__(256) prep_fuse(
    const float* __restrict__ W1, const float* __restrict__ b1,
    const float* __restrict__ W2, const float* __restrict__ b2,
    const float* __restrict__ Wq, const float* __restrict__ bq,
    const float* __restrict__ Wk, const float* __restrict__ bk)
{
    int h   = blockIdx.x;
    int sel = blockIdx.y;
    int c0  = blockIdx.z * 64;
    const float* Wh   = sel ? W2 : W1;
    const float* bh_  = sel ? b2 : b1;
    const float* Wsrc = sel ? Wk : Wq;
    const float* bsrc = sel ? bk : bq;
    float* Wout = sel ? g_Wfk : g_Wfq;
    float* bout = sel ? g_bfk : g_bfq;
    __shared__ float Ws[DD][DD + 1];
    __shared__ float Ts[DD][DD + 1];
    int tid = threadIdx.x;
    for (int t = tid; t < DD * DD; t += 256) {
        Ws[t >> 6][t & 63] = Wh[t];
        Ts[t >> 6][t & 63] = Wsrc[(h * DD + (t >> 6)) * HIDN + c0 + (t & 63)];
    }
    __syncthreads();
    if (blockIdx.z == 0 && tid < DD) {
        float acc = bh_[tid];
        for (int j = 0; j < DD; j++) acc += Ws[tid][j] * bsrc[h * DD + j];
        bout[h * DD + tid] = acc;
    }
    int i = tid & 63;
    int g = tid >> 6;
#pragma unroll
    for (int cc = 0; cc < 16; cc++) {
        int c = g * 16 + cc;
        float acc = 0.f;
#pragma unroll 8
        for (int j = 0; j < DD; j++) acc = fmaf(Ws[i][j], Ts[j][c], acc);
        Wout[(h * DD + i) * HIDN + c0 + c] = acc;
    }
}

// ---------------- tf32 TC GEMM (templated tile height): out = X @ W^T + bias ----
// BM=64: 8 warps as 4m x 2n (warp 16x32). BM=32: 8 warps as 2m x 4n (warp 16x16).
// mode 0: plain fp32 [m, HIDN]; mode 3: Q-featurize; mode 4: K-featurize+ck; mode 5: V->half [d][l]
template<int BM>
__global__ void __launch_bounds__(256) gemm_tc(
    const float* __restrict__ X0, const float* __restrict__ Wm0, const float* __restrict__ B0, float* __restrict__ O0, int md0,
    const float* __restrict__ X1, const float* __restrict__ Wm1, const float* __restrict__ B1, float* __restrict__ O1, int md1,
    const float* __restrict__ X2, const float* __restrict__ Wm2, const float* __restrict__ B2, float* __restrict__ O2, int md2,
    const float* __restrict__ vw)
{
    const int BK = 32;
    const int NT = (BM == 64) ? 4 : 2;
    int z = blockIdx.z;
    const float* X  = z == 0 ? X0  : (z == 1 ? X1  : X2);
    const float* W  = z == 0 ? Wm0 : (z == 1 ? Wm1 : Wm2);
    const float* Bi = z == 0 ? B0  : (z == 1 ? B1  : B2);
    float*       O  = z == 0 ? O0  : (z == 1 ? O1  : O2);
    int        mode = z == 0 ? md0 : (z == 1 ? md1 : md2);

    __shared__ union {
        struct { unsigned X[BM * 36]; unsigned W[64 * 36]; } st;
        float out[BM * 68];
    } sm;

    int tid = threadIdx.x;
    int lane = tid & 31;
    int warp = tid >> 5;
    int warp_m = (BM == 64) ? (warp & 3) * 16 : (warp & 1) * 16;
    int warp_n = (BM == 64) ? (warp >> 2) * 32 : (warp >> 1) * 16;
    int gr = lane >> 2;
    int tg = lane & 3;
    int m0 = blockIdx.y * BM, n0 = blockIdx.x * 64;

    int ldr  = tid >> 3;              // 0..31
    int ldc4 = tid & 7;               // 0..7

    float acc[NT][4];
#pragma unroll
    for (int nt = 0; nt < NT; nt++)
#pragma unroll
        for (int i = 0; i < 4; i++) acc[nt][i] = 0.f;

    // prefetch tile 0
    float4 px[BM / 32], pw[2];
#pragma unroll
    for (int i = 0; i < BM / 32; i++)
        px[i] = *(const float4*)&X[(m0 + ldr + i * 32) * HIDN + ldc4 * 4];
#pragma unroll
    for (int i = 0; i < 2; i++)
        pw[i] = *(const float4*)&W[(n0 + ldr + i * 32) * HIDN + ldc4 * 4];

    for (int kk = 0; kk < HIDN; kk += BK) {
        // stage prefetched tile (fp32 -> tf32, RN)
#pragma unroll
        for (int i = 0; i < BM / 32; i++) {
            int r = ldr + i * 32;
            uint4 u;
            u.x = f2tf32(px[i].x); u.y = f2tf32(px[i].y); u.z = f2tf32(px[i].z); u.w = f2tf32(px[i].w);
            *(uint4*)&sm.st.X[r * 36 + ldc4 * 4] = u;
        }
#pragma unroll
        for (int i = 0; i < 2; i++) {
            int r = ldr + i * 32;
            uint4 u;
            u.x = f2tf32(pw[i].x); u.y = f2tf32(pw[i].y); u.z = f2tf32(pw[i].z); u.w = f2tf32(pw[i].w);
            *(uint4*)&sm.st.W[r * 36 + ldc4 * 4] = u;
        }
        __syncthreads();
        // prefetch next tile while MMAs run
        if (kk + BK < HIDN) {
#pragma unroll
            for (int i = 0; i < BM / 32; i++)
                px[i] = *(const float4*)&X[(m0 + ldr + i * 32) * HIDN + kk + BK + ldc4 * 4];
#pragma unroll
            for (int i = 0; i < 2; i++)
                pw[i] = *(const float4*)&W[(n0 + ldr + i * 32) * HIDN + kk + BK + ldc4 * 4];
        }
#pragma unroll
        for (int k8 = 0; k8 < 4; k8++) {
            int kb = k8 * 8;
            unsigned a[4], b[NT][2];
            a[0] = sm.st.X[(warp_m + gr    ) * 36 + kb + tg];
            a[1] = sm.st.X[(warp_m + gr + 8) * 36 + kb + tg];
            a[2] = sm.st.X[(warp_m + gr    ) * 36 + kb + tg + 4];
            a[3] = sm.st.X[(warp_m + gr + 8) * 36 + kb + tg + 4];
#pragma unroll
            for (int nt = 0; nt < NT; nt++) {
                int rn = warp_n + nt * 8 + gr;
                b[nt][0] = sm.st.W[rn * 36 + kb + tg];
                b[nt][1] = sm.st.W[rn * 36 + kb + tg + 4];
            }
#pragma unroll
            for (int nt = 0; nt < NT; nt++)
                mma_tf32(acc[nt], a, b[nt]);
        }
        __syncthreads();
    }

    // epilogue: acc -> smem tile (overlays staging buffers)
#pragma unroll
    for (int nt = 0; nt < NT; nt++) {
        int col = warp_n + nt * 8 + 2 * tg;
        sm.out[(warp_m + gr    ) * 68 + col    ] = acc[nt][0];
        sm.out[(warp_m + gr    ) * 68 + col + 1] = acc[nt][1];
        sm.out[(warp_m + gr + 8) * 68 + col    ] = acc[nt][2];
        sm.out[(warp_m + gr + 8) * 68 + col + 1] = acc[nt][3];
    }
    __syncthreads();

    int b_ = m0 / LL, l0 = m0 - b_ * LL;
    int h = n0 >> 6;
    int bh = b_ * HH + h;

    if (mode == 0) {
#pragma unroll
        for (int i = 0; i < BM / 16; i++) {
            int idx = tid + i * 256;
            int r = idx >> 4, c4 = idx & 15;
            float4 v = *(float4*)&sm.out[r * 68 + c4 * 4];
            float4 b4 = *(const float4*)&Bi[n0 + c4 * 4];
            v.x += b4.x; v.y += b4.y; v.z += b4.z; v.w += b4.w;
            *(float4*)&O[(m0 + r) * HIDN + n0 + c4 * 4] = v;
        }
    } else if (mode == 3 || mode == 4) {
        __half* Fdst = (mode == 3 ? g_FQ : g_FK) + (size_t)(bh * LL + l0) * FD;
#pragma unroll
        for (int i = 0; i < BM / 16; i++) {
            int idx = tid + i * 256;
            int r = idx >> 4, c4 = idx & 15;
            int d0 = c4 * 4;
            float4 v = *(float4*)&sm.out[r * 68 + d0];
            float4 b4 = *(const float4*)&Bi[n0 + d0];
            float t0 = tanh_ap(v.x + b4.x), t1 = tanh_ap(v.y + b4.y);
            float t2 = tanh_ap(v.z + b4.z), t3 = tanh_ap(v.w + b4.w);
            float w0 = __ldg(&vw[d0]), w1 = __ldg(&vw[d0 + 1]);
            float w2 = __ldg(&vw[d0 + 2]), w3 = __ldg(&vw[d0 + 3]);
            __half* row = Fdst + (size_t)r * FD;
            if (mode == 3) {
                // FQ = [ta^2, vw*ta, ta^3, vw*ta^2]
                *(__half2*)&row[0*64 + d0    ] = __floats2half2_rn(t0*t0, t1*t1);
                *(__half2*)&row[0*64 + d0 + 2] = __floats2half2_rn(t2*t2, t3*t3);
                *(__half2*)&row[1*64 + d0    ] = __floats2half2_rn(w0*t0, w1*t1);
                *(__half2*)&row[1*64 + d0 + 2] = __floats2half2_rn(w2*t2, w3*t3);
                *(__half2*)&row[2*64 + d0    ] = __floats2half2_rn(t0*t0*t0, t1*t1*t1);
                *(__half2*)&row[2*64 + d0 + 2] = __floats2half2_rn(t2*t2*t2, t3*t3*t3);
                *(__half2*)&row[3*64 + d0    ] = __floats2half2_rn(w0*t0*t0, w1*t1*t1);
                *(__half2*)&row[3*64 + d0 + 2] = __floats2half2_rn(w2*t2*t2, w3*t3*t3);
            } else {
                // FK = [-vw*tb, -tb^2, vw*tb^2, tb^3]
                *(__half2*)&row[0*64 + d0    ] = __floats2half2_rn(-w0*t0, -w1*t1);
                *(__half2*)&row[0*64 + d0 + 2] = __floats2half2_rn(-w2*t2, -w3*t3);
                *(__half2*)&row[1*64 + d0    ] = __floats2half2_rn(-t0*t0, -t1*t1);
                *(__half2*)&row[1*64 + d0 + 2] = __floats2half2_rn(-t2*t2, -t3*t3);
                *(__half2*)&row[2*64 + d0    ] = __floats2half2_rn(w0*t0*t0, w1*t1*t1);
                *(__half2*)&row[2*64 + d0 + 2] = __floats2half2_rn(w2*t2*t2, w3*t3*t3);
                *(__half2*)&row[3*64 + d0    ] = __floats2half2_rn(t0*t0*t0, t1*t1*t1);
                *(__half2*)&row[3*64 + d0 + 2] = __floats2half2_rn(t2*t2*t2, t3*t3*t3);
                float cp = w0*t0 + w1*t1 + w2*t2 + w3*t3;
#pragma unroll
                for (int o = 1; o < 16; o <<= 1) cp += __shfl_xor_sync(0xffffffffu, cp, o);
                if ((tid & 15) == 0) g_ck[bh * LL + l0 + r] = cp;
            }
        }
    } else {
        // mode 5: V -> half, transposed [bh][d][l]
        __half* base = g_Vh + (size_t)bh * DD * LL;
#pragma unroll
        for (int i = 0; i < BM / 16; i++) {
            int idx = tid + i * 256;
            int d = idx >> 4, l4 = idx & 15;
            float bd = __ldg(&Bi[n0 + d]);
            float v0 = sm.out[(l4 * 4 + 0) * 68 + d] + bd;
            float v1 = sm.out[(l4 * 4 + 1) * 68 + d] + bd;
            float v2 = sm.out[(l4 * 4 + 2) * 68 + d] + bd;
            float v3 = sm.out[(l4 * 4 + 3) * 68 + d] + bd;
            *(__half2*)&base[d * LL + l0 + l4 * 4    ] = __floats2half2_rn(v0, v1);
            *(__half2*)&base[d * LL + l0 + l4 * 4 + 2] = __floats2half2_rn(v2, v3);
        }
    }
}

// ---------------- attention: E = FQ@FK^T + ck -> softmax -> X = P@V (f16 MMA) ----
#define LLP 392
#define FDP 264
#define VHS 72
#define EOFF  0
#define UOFF  (32*LLP*4)                       // 50176
#define FQOFF UOFF
#define FKOFF (UOFF + 32*FDP*2)                // +16896
#define VHOFF UOFF
#define CKOFF (UOFF + 32*FDP*2 + 64*FDP*2)     // 100864
#define MOFF  (CKOFF + LL*4)                   // 102400
#define SMEM_ATTN (MOFF + LL*4)                // 103936

__global__ void __launch_bounds__(256) attn_fused(
    const int* __restrict__ mask, float* __restrict__ attn)
{
    extern __shared__ char smraw[];
    float*  E  = (float*) (smraw + EOFF);   // [32][LLP]
    __half* FQ = (__half*)(smraw + FQOFF);  // [32][FDP]
    __half* FK = (__half*)(smraw + FKOFF);  // [64][FDP]
    __half* Vh = (__half*)(smraw + VHOFF);  // [64][VHS]
    float*  CK = (float*) (smraw + CKOFF);
    int*    M  = (int*)   (smraw + MOFF);

    int tid = threadIdx.x;
    int lane = tid & 31, warp = tid >> 5;
    int wm = (warp & 1) * 16;
    int wn = (warp >> 1) * 16;
    int gr = lane >> 2, tg = lane & 3;
    int bh = blockIdx.y, b = bh >> 3, h = bh & 7;
    int q0 = blockIdx.x * 32;

    for (int j = tid; j < LL; j += 256) { M[j] = mask[b * LL + j]; CK[j] = g_ck[bh * LL + j]; }
    {
        const unsigned* s32 = (const unsigned*)(g_FQ + (size_t)(bh * LL + q0) * FD);
#pragma unroll
        for (int i = 0; i < 16; i++) {
            int idx = tid + i * 256;
            int r = idx >> 7, c2 = idx & 127;
            *(unsigned*)&FQ[r * FDP + c2 * 2] = s32[r * 128 + c2];
        }
    }

    for (int c = 0; c < 6; c++) {
        __syncthreads();
        {
            const unsigned* s32 = (const unsigned*)(g_FK + (size_t)(bh * LL + c * 64) * FD);
#pragma unroll
            for (int i = 0; i < 32; i++) {
                int idx = tid + i * 256;
                int r = idx >> 7, c2 = idx & 127;
                *(unsigned*)&FK[r * FDP + c2 * 2] = s32[r * 128 + c2];
            }
        }
        __syncthreads();
        float eacc[2][4];
#pragma unroll
        for (int nt = 0; nt < 2; nt++)
#pragma unroll
            for (int i = 0; i < 4; i++) eacc[nt][i] = 0.f;
#pragma unroll
        for (int ks = 0; ks < 16; ks++) {
            int k0 = ks * 16;
            unsigned a[4], bf[2][2];
            a[0] = *(const unsigned*)&FQ[(wm + gr    ) * FDP + k0 + 2 * tg];
            a[1] = *(const unsigned*)&FQ[(wm + gr + 8) * FDP + k0 + 2 * tg];
            a[2] = *(const unsigned*)&FQ[(wm + gr    ) * FDP + k0 + 2 * tg + 8];
            a[3] = *(const unsigned*)&FQ[(wm + gr + 8) * FDP + k0 + 2 * tg + 8];
#pragma unroll
            for (int nt = 0; nt < 2; nt++) {
                int rn = wn + nt * 8 + gr;
                bf[nt][0] = *(const unsigned*)&FK[rn * FDP + k0 + 2 * tg];
                bf[nt][1] = *(const unsigned*)&FK[rn * FDP + k0 + 2 * tg + 8];
            }
            mma_f16(eacc[0], a, bf[0]);
            mma_f16(eacc[1], a, bf[1]);
        }
#pragma unroll
        for (int nt = 0; nt < 2; nt++) {
            int col = c * 64 + wn + nt * 8 + 2 * tg;
            *(float2*)&E[(wm + gr    ) * LLP + col] = make_float2(eacc[nt][0], eacc[nt][1]);
            *(float2*)&E[(wm + gr + 8) * LLP + col] = make_float2(eacc[nt][2], eacc[nt][3]);
        }
    }
    __syncthreads();

    {
        int row = tid >> 3, lx = tid & 7;
        float mx = -3.0e38f;
        for (int i = 0; i < 48; i++) {
            int j = lx + i * 8;
            float e = E[row * LLP + j] + CK[j];
            if (M[j] == 0) e = -1e10f;
            E[row * LLP + j] = e;
            mx = fmaxf(mx, e);
        }
#pragma unroll
        for (int o = 4; o > 0; o >>= 1) mx = fmaxf(mx, __shfl_xor_sync(0xffffffffu, mx, o));
        float sum = 0.f;
        for (int i = 0; i < 48; i++) {
            int j = lx + i * 8;
            float p = __expf(E[row * LLP + j] - mx);
            sum += p;
            E[row * LLP + j] = p;
        }
#pragma unroll
        for (int o = 4; o > 0; o >>= 1) sum += __shfl_xor_sync(0xffffffffu, sum, o);
        float inv = __frcp_rn(sum);
        for (int i = 0; i < 48; i++) E[row * LLP + lx + i * 8] *= inv;
    }
    __syncthreads();

    {
        float* dst = attn + (size_t)(bh * LL + q0) * LL;
        for (int idx = tid; idx < 32 * LL; idx += 256) {
            int r = idx / LL, j = idx - r * LL;
            dst[r * LL + j] = E[r * LLP + j];
        }
    }

    float xacc[2][4];
#pragma unroll
    for (int nt = 0; nt < 2; nt++)
#pragma unroll
        for (int i = 0; i < 4; i++) xacc[nt][i] = 0.f;

    for (int c = 0; c < 6; c++) {
        __syncthreads();
        {
            const unsigned* s32 = (const unsigned*)(g_Vh + (size_t)bh * DD * LL + c * 64);
#pragma unroll
            for (int i = 0; i < 8; i++) {
                int idx = tid + i * 256;
                int d = idx >> 5, c2 = idx & 31;
                *(unsigned*)&Vh[d * VHS + c2 * 2] = s32[d * (LL / 2) + c2];
            }
        }
        __syncthreads();
#pragma unroll
        for (int ks = 0; ks < 4; ks++) {
            int kg = c * 64 + ks * 16;
            unsigned a[4], bf[2][2];
            float2 p0 = *(const float2*)&E[(wm + gr    ) * LLP + kg + 2 * tg];
            float2 p1 = *(const float2*)&E[(wm + gr + 8) * LLP + kg + 2 * tg];
            float2 p2 = *(const float2*)&E[(wm + gr    ) * LLP + kg + 2 * tg + 8];
            float2 p3 = *(const float2*)&E[(wm + gr + 8) * LLP + kg + 2 * tg + 8];
            a[0] = h2u(__floats2half2_rn(p0.x, p0.y));
            a[1] = h2u(__floats2half2_rn(p1.x, p1.y));
            a[2] = h2u(__floats2half2_rn(p2.x, p2.y));
            a[3] = h2u(__floats2half2_rn(p3.x, p3.y));
            int kl = ks * 16 + 2 * tg;
#pragma unroll
            for (int nt = 0; nt < 2; nt++) {
                int rn = wn + nt * 8 + gr;
                bf[nt][0] = *(const unsigned*)&Vh[rn * VHS + kl];
                bf[nt][1] = *(const unsigned*)&Vh[rn * VHS + kl + 8];
            }
            mma_f16(xacc[0], a, bf[0]);
            mma_f16(xacc[1], a, bf[1]);
        }
    }

    {
        int q = q0 + wm + gr;
#pragma unroll
        for (int nt = 0; nt < 2; nt++) {
            int d = h * DD + wn + nt * 8 + 2 * tg;
            *(float2*)&g_X[(size_t)(b * LL + q    ) * HIDN + d] = make_float2(xacc[nt][0], xacc[nt][1]);
            *(float2*)&g_X[(size_t)(b * LL + q + 8) * HIDN + d] = make_float2(xacc[nt][2], xacc[nt][3]);
        }
    }
}

extern "C" void kernel_launch(void* const* d_in, const int* in_sizes, int n_in,
                              void* d_out, int out_size)
{
    const float* query = (const float*)d_in[0];
    const float* key_  = (const float*)d_in[1];
    const float* value = (const float*)d_in[2];
    const int*   mask  = (const int*)  d_in[3];
    const float* Wq = (const float*)d_in[4];
    const float* bq = (const float*)d_in[5];
    const float* Wk = (const float*)d_in[6];
    const float* bk = (const float*)d_in[7];
    const float* Wv = (const float*)d_in[8];
    const float* bv = (const float*)d_in[9];
    const float* Wo = (const float*)d_in[10];
    const float* bo = (const float*)d_in[11];
    const float* W1 = (const float*)d_in[12];
    const float* b1 = (const float*)d_in[13];
    const float* W2 = (const float*)d_in[14];
    const float* b2 = (const float*)d_in[15];
    const float* vw = (const float*)d_in[16];
    (void)d_in[17];
    (void)in_sizes; (void)n_in;

    float* out = (float*)d_out;

    float *gX, *gA, *gWfq, *gWfk, *gbfq, *gbfk;
    cudaGetSymbolAddress((void**)&gX,   g_X);
    cudaGetSymbolAddress((void**)&gA,   g_attn);
    cudaGetSymbolAddress((void**)&gWfq, g_Wfq);
    cudaGetSymbolAddress((void**)&gWfk, g_Wfk);
    cudaGetSymbolAddress((void**)&gbfq, g_bfq);
    cudaGetSymbolAddress((void**)&gbfk, g_bfk);

    float* attn_dst = (out_size >= X_ELEMS + A_ELEMS) ? (out + X_ELEMS) : gA;

    cudaFuncSetAttribute(attn_fused, cudaFuncAttributeMaxDynamicSharedMemorySize, SMEM_ATTN);

    // 1) fuse W1@Wq and W2@Wk (128 blocks)
    prep_fuse<<<dim3(HH, 2, HIDN / 64), 256>>>(W1, b1, W2, b2, Wq, bq, Wk, bk);

    // 2) projections + featurization — tf32 TC, 288 blocks (BM=64)
    gemm_tc<64><<<dim3(HIDN / 64, MROWS / 64, 3), 256>>>(
        query, gWfq, gbfq, nullptr, 3,
        key_,  gWfk, gbfk, nullptr, 4,
        value, Wv,   bv,   nullptr, 5,
        vw);

    // 3) attention: E-mma + softmax + AV-mma (192 blocks, dyn smem)
    attn_fused<<<dim3(LL / 32, BH), 256, SMEM_ATTN>>>(mask, attn_dst);

    // 4) output projection — tf32 TC, 192 blocks (BM=32 -> full SM coverage)
    gemm_tc<32><<<dim3(HIDN / 64, MROWS / 32, 1), 256>>>(
        gX, Wo, bo, out, 0,
        gX, Wo, bo, out, 0,
        gX, Wo, bo, out, 0,
        vw);
}

// round 13
// speedup vs baseline: 1.0847x; 1.0038x over previous
#include <cuda_runtime.h>
#include <cuda_fp16.h>

#define BB 2
#define LL 384
#define HH 8
#define DD 64
#define HIDN 512
#define BH (BB*HH)          // 16
#define MROWS (BB*LL)       // 768
#define X_ELEMS (MROWS*HIDN)    // 393216
#define A_ELEMS (BH*LL*LL)      // 2359296
#define FD 256              // feature dim (4 segments x 64)

// -------- scratch (no dynamic allocation allowed) --------
__device__ __half g_FQ[BH*LL*FD];   // [bh][l][256]  q-side features
__device__ __half g_FK[BH*LL*FD];   // [bh][l][256]  k-side features
__device__ __half g_Vh[BH*DD*LL];   // [bh][d][l]    V transposed, half
__device__ float  g_ck[BH*LL];      // per-k energy constant
__device__ float  g_X [X_ELEMS];
__device__ float  g_attn[A_ELEMS];
__device__ float  g_Wfq[HIDN*HIDN];
__device__ float  g_Wfk[HIDN*HIDN];
__device__ float  g_bfq[HIDN];
__device__ float  g_bfk[HIDN];

__device__ __forceinline__ float tanh_ap(float x) {
    float y; asm("tanh.approx.f32 %0, %1;" : "=f"(y) : "f"(x)); return y;
}
__device__ __forceinline__ unsigned f2tf32(float f) {
    unsigned u; asm("cvt.rna.tf32.f32 %0, %1;" : "=r"(u) : "f"(f)); return u;
}
__device__ __forceinline__ void mma_tf32(float* c, const unsigned* a, const unsigned* b) {
    asm volatile(
        "mma.sync.aligned.m16n8k8.row.col.f32.tf32.tf32.f32 "
        "{%0,%1,%2,%3}, {%4,%5,%6,%7}, {%8,%9}, {%0,%1,%2,%3};"
        : "+f"(c[0]), "+f"(c[1]), "+f"(c[2]), "+f"(c[3])
        : "r"(a[0]), "r"(a[1]), "r"(a[2]), "r"(a[3]), "r"(b[0]), "r"(b[1]));
}
__device__ __forceinline__ void mma_f16(float* c, const unsigned* a, const unsigned* b) {
    asm volatile(
        "mma.sync.aligned.m16n8k16.row.col.f32.f16.f16.f32 "
        "{%0,%1,%2,%3}, {%4,%5,%6,%7}, {%8,%9}, {%0,%1,%2,%3};"
        : "+f"(c[0]), "+f"(c[1]), "+f"(c[2]), "+f"(c[3])
        : "r"(a[0]), "r"(a[1]), "r"(a[2]), "r"(a[3]), "r"(b[0]), "r"(b[1]));
}
__device__ __forceinline__ unsigned h2u(__half2 v) { return *(unsigned*)&v; }

// ---------------- prep: fused per-head weights ----------------
__global__ void __launch_bounds__(256) prep_fuse(
    const float* __restrict__ W1, const float* __restrict__ b1,
    const float* __restrict__ W2, const float* __restrict__ b2,
    const float* __restrict__ Wq, const float* __restrict__ bq,
    const float* __restrict__ Wk, const float* __restrict__ bk)
{
    int h   = blockIdx.x;
    int sel = blockIdx.y;
    int c0  = blockIdx.z * 64;
    const float* Wh   = sel ? W2 : W1;
    const float* bh_  = sel ? b2 : b1;
    const float* Wsrc = sel ? Wk : Wq;
    const float* bsrc = sel ? bk : bq;
    float* Wout = sel ? g_Wfk : g_Wfq;
    float* bout = sel ? g_bfk : g_bfq;
    __shared__ float Ws[DD][DD + 1];
    __shared__ float Ts[DD][DD + 1];
    int tid = threadIdx.x;
    for (int t = tid; t < DD * DD; t += 256) {
        Ws[t >> 6][t & 63] = Wh[t];
        Ts[t >> 6][t & 63] = Wsrc[(h * DD + (t >> 6)) * HIDN + c0 + (t & 63)];
    }
    __syncthreads();
    if (blockIdx.z == 0 && tid < DD) {
        float acc = bh_[tid];
        for (int j = 0; j < DD; j++) acc += Ws[tid][j] * bsrc[h * DD + j];
        bout[h * DD + tid] = acc;
    }
    int i = tid & 63;
    int g = tid >> 6;
#pragma unroll
    for (int cc = 0; cc < 16; cc++) {
        int c = g * 16 + cc;
        float acc = 0.f;
#pragma unroll 8
        for (int j = 0; j < DD; j++) acc = fmaf(Ws[i][j], Ts[j][c], acc);
        Wout[(h * DD + i) * HIDN + c0 + c] = acc;
    }
}

// ---------------- tf32 TC GEMM v4: BK=64 (halved syncs, latency covered) ----------------
// BM=64: 8 warps as 4m x 2n (warp 16x32). BM=32: 8 warps as 2m x 4n (warp 16x16).
// mode 0: plain fp32 [m, HIDN]; mode 3: Q-featurize; mode 4: K-featurize+ck; mode 5: V->half [d][l]
template<int BM>
__global__ void __launch_bounds__(256) gemm_tc(
    const float* __restrict__ X0, const float* __restrict__ Wm0, const float* __restrict__ B0, float* __restrict__ O0, int md0,
    const float* __restrict__ X1, const float* __restrict__ Wm1, const float* __restrict__ B1, float* __restrict__ O1, int md1,
    const float* __restrict__ X2, const float* __restrict__ Wm2, const float* __restrict__ B2, float* __restrict__ O2, int md2,
    const float* __restrict__ vw)
{
    const int BK = 64;
    const int NIT = HIDN / BK;        // 8
    const int NT = (BM == 64) ? 4 : 2;
    const int NLX = BM / 16;          // float4 X loads per thread (4 or 2)
    int z = blockIdx.z;
    const float* X  = z == 0 ? X0  : (z == 1 ? X1  : X2);
    const float* W  = z == 0 ? Wm0 : (z == 1 ? Wm1 : Wm2);
    const float* Bi = z == 0 ? B0  : (z == 1 ? B1  : B2);
    float*       O  = z == 0 ? O0  : (z == 1 ? O1  : O2);
    int        mode = z == 0 ? md0 : (z == 1 ? md1 : md2);

    __shared__ union {
        struct { unsigned X[BM * 68]; unsigned W[64 * 68]; } st;
        float out[BM * 68];
    } sm;

    int tid = threadIdx.x;
    int lane = tid & 31;
    int warp = tid >> 5;
    int warp_m = (BM == 64) ? (warp & 3) * 16 : (warp & 1) * 16;
    int warp_n = (BM == 64) ? (warp >> 2) * 32 : (warp >> 1) * 16;
    int gr = lane >> 2;
    int tg = lane & 3;
    int m0 = blockIdx.y * BM, n0 = blockIdx.x * 64;

    float acc[NT][4];
#pragma unroll
    for (int nt = 0; nt < NT; nt++)
#pragma unroll
        for (int i = 0; i < 4; i++) acc[nt][i] = 0.f;

    // prefetch tile 0 (full 64-wide K slab)
    float4 px[NLX], pw[4];
#pragma unroll
    for (int i = 0; i < NLX; i++) {
        int idx = tid + i * 256;
        int r = idx >> 4, c4 = idx & 15;
        px[i] = *(const float4*)&X[(m0 + r) * HIDN + c4 * 4];
    }
#pragma unroll
    for (int i = 0; i < 4; i++) {
        int idx = tid + i * 256;
        int r = idx >> 4, c4 = idx & 15;
        pw[i] = *(const float4*)&W[(n0 + r) * HIDN + c4 * 4];
    }

    for (int it = 0; it < NIT; it++) {
        // stage prefetched tile (fp32 -> tf32, RN)
#pragma unroll
        for (int i = 0; i < NLX; i++) {
            int idx = tid + i * 256;
            int r = idx >> 4, c4 = idx & 15;
            uint4 u;
            u.x = f2tf32(px[i].x); u.y = f2tf32(px[i].y); u.z = f2tf32(px[i].z); u.w = f2tf32(px[i].w);
            *(uint4*)&sm.st.X[r * 68 + c4 * 4] = u;
        }
#pragma unroll
        for (int i = 0; i < 4; i++) {
            int idx = tid + i * 256;
            int r = idx >> 4, c4 = idx & 15;
            uint4 u;
            u.x = f2tf32(pw[i].x); u.y = f2tf32(pw[i].y); u.z = f2tf32(pw[i].z); u.w = f2tf32(pw[i].w);
            *(uint4*)&sm.st.W[r * 68 + c4 * 4] = u;
        }
        __syncthreads();
        // prefetch next slab while 8 k8-steps of MMA run
        if (it + 1 < NIT) {
            int kk = (it + 1) * BK;
#pragma unroll
            for (int i = 0; i < NLX; i++) {
                int idx = tid + i * 256;
                int r = idx >> 4, c4 = idx & 15;
                px[i] = *(const float4*)&X[(m0 + r) * HIDN + kk + c4 * 4];
            }
#pragma unroll
            for (int i = 0; i < 4; i++) {
                int idx = tid + i * 256;
                int r = idx >> 4, c4 = idx & 15;
                pw[i] = *(const float4*)&W[(n0 + r) * HIDN + kk + c4 * 4];
            }
        }
#pragma unroll
        for (int k8 = 0; k8 < 8; k8++) {
            int kb = k8 * 8;
            unsigned a[4], b[NT][2];
            a[0] = sm.st.X[(warp_m + gr    ) * 68 + kb + tg];
            a[1] = sm.st.X[(warp_m + gr + 8) * 68 + kb + tg];
            a[2] = sm.st.X[(warp_m + gr    ) * 68 + kb + tg + 4];
            a[3] = sm.st.X[(warp_m + gr + 8) * 68 + kb + tg + 4];
#pragma unroll
            for (int nt = 0; nt < NT; nt++) {
                int rn = warp_n + nt * 8 + gr;
                b[nt][0] = sm.st.W[rn * 68 + kb + tg];
                b[nt][1] = sm.st.W[rn * 68 + kb + tg + 4];
            }
#pragma unroll
            for (int nt = 0; nt < NT; nt++)
                mma_tf32(acc[nt], a, b[nt]);
        }
        __syncthreads();
    }

    // epilogue: acc -> smem tile (overlays staging buffers)
#pragma unroll
    for (int nt = 0; nt < NT; nt++) {
        int col = warp_n + nt * 8 + 2 * tg;
        sm.out[(warp_m + gr    ) * 68 + col    ] = acc[nt][0];
        sm.out[(warp_m + gr    ) * 68 + col + 1] = acc[nt][1];
        sm.out[(warp_m + gr + 8) * 68 + col    ] = acc[nt][2];
        sm.out[(warp_m + gr + 8) * 68 + col + 1] = acc[nt][3];
    }
    __syncthreads();

    int b_ = m0 / LL, l0 = m0 - b_ * LL;
    int h = n0 >> 6;
    int bh = b_ * HH + h;

    if (mode == 0) {
#pragma unroll
        for (int i = 0; i < BM / 16; i++) {
            int idx = tid + i * 256;
            int r = idx >> 4, c4 = idx & 15;
            float4 v = *(float4*)&sm.out[r * 68 + c4 * 4];
            float4 b4 = *(const float4*)&Bi[n0 + c4 * 4];
            v.x += b4.x; v.y += b4.y; v.z += b4.z; v.w += b4.w;
            *(float4*)&O[(m0 + r) * HIDN + n0 + c4 * 4] = v;
        }
    } else if (mode == 3 || mode == 4) {
        __half* Fdst = (mode == 3 ? g_FQ : g_FK) + (size_t)(bh * LL + l0) * FD;
#pragma unroll
        for (int i = 0; i < BM / 16; i++) {
            int idx = tid + i * 256;
            int r = idx >> 4, c4 = idx & 15;
            int d0 = c4 * 4;
            float4 v = *(float4*)&sm.out[r * 68 + d0];
            float4 b4 = *(const float4*)&Bi[n0 + d0];
            float t0 = tanh_ap(v.x + b4.x), t1 = tanh_ap(v.y + b4.y);
            float t2 = tanh_ap(v.z + b4.z), t3 = tanh_ap(v.w + b4.w);
            float w0 = __ldg(&vw[d0]), w1 = __ldg(&vw[d0 + 1]);
            float w2 = __ldg(&vw[d0 + 2]), w3 = __ldg(&vw[d0 + 3]);
            __half* row = Fdst + (size_t)r * FD;
            if (mode == 3) {
                // FQ = [ta^2, vw*ta, ta^3, vw*ta^2]
                *(__half2*)&row[0*64 + d0    ] = __floats2half2_rn(t0*t0, t1*t1);
                *(__half2*)&row[0*64 + d0 + 2] = __floats2half2_rn(t2*t2, t3*t3);
                *(__half2*)&row[1*64 + d0    ] = __floats2half2_rn(w0*t0, w1*t1);
                *(__half2*)&row[1*64 + d0 + 2] = __floats2half2_rn(w2*t2, w3*t3);
                *(__half2*)&row[2*64 + d0    ] = __floats2half2_rn(t0*t0*t0, t1*t1*t1);
                *(__half2*)&row[2*64 + d0 + 2] = __floats2half2_rn(t2*t2*t2, t3*t3*t3);
                *(__half2*)&row[3*64 + d0    ] = __floats2half2_rn(w0*t0*t0, w1*t1*t1);
                *(__half2*)&row[3*64 + d0 + 2] = __floats2half2_rn(w2*t2*t2, w3*t3*t3);
            } else {
                // FK = [-vw*tb, -tb^2, vw*tb^2, tb^3]
                *(__half2*)&row[0*64 + d0    ] = __floats2half2_rn(-w0*t0, -w1*t1);
                *(__half2*)&row[0*64 + d0 + 2] = __floats2half2_rn(-w2*t2, -w3*t3);
                *(__half2*)&row[1*64 + d0    ] = __floats2half2_rn(-t0*t0, -t1*t1);
                *(__half2*)&row[1*64 + d0 + 2] = __floats2half2_rn(-t2*t2, -t3*t3);
                *(__half2*)&row[2*64 + d0    ] = __floats2half2_rn(w0*t0*t0, w1*t1*t1);
                *(__half2*)&row[2*64 + d0 + 2] = __floats2half2_rn(w2*t2*t2, w3*t3*t3);
                *(__half2*)&row[3*64 + d0    ] = __floats2half2_rn(t0*t0*t0, t1*t1*t1);
                *(__half2*)&row[3*64 + d0 + 2] = __floats2half2_rn(t2*t2*t2, t3*t3*t3);
                float cp = w0*t0 + w1*t1 + w2*t2 + w3*t3;
#pragma unroll
                for (int o = 1; o < 16; o <<= 1) cp += __shfl_xor_sync(0xffffffffu, cp, o);
                if ((tid & 15) == 0) g_ck[bh * LL + l0 + r] = cp;
            }
        }
    } else {
        // mode 5: V -> half, transposed [bh][d][l]
        __half* base = g_Vh + (size_t)bh * DD * LL;
#pragma unroll
        for (int i = 0; i < BM / 16; i++) {
            int idx = tid + i * 256;
            int d = idx >> 4, l4 = idx & 15;
            float bd = __ldg(&Bi[n0 + d]);
            float v0 = sm.out[(l4 * 4 + 0) * 68 + d] + bd;
            float v1 = sm.out[(l4 * 4 + 1) * 68 + d] + bd;
            float v2 = sm.out[(l4 * 4 + 2) * 68 + d] + bd;
            float v3 = sm.out[(l4 * 4 + 3) * 68 + d] + bd;
            *(__half2*)&base[d * LL + l0 + l4 * 4    ] = __floats2half2_rn(v0, v1);
            *(__half2*)&base[d * LL + l0 + l4 * 4 + 2] = __floats2half2_rn(v2, v3);
        }
    }
}

// ---------------- attention: E = FQ@FK^T + ck -> softmax -> X = P@V (f16 MMA) ----
#define LLP 392
#define FDP 264
#define VHS 72
#define EOFF  0
#define UOFF  (32*LLP*4)                       // 50176
#define FQOFF UOFF
#define FKOFF (UOFF + 32*FDP*2)                // +16896
#define VHOFF UOFF
#define CKOFF (UOFF + 32*FDP*2 + 64*FDP*2)     // 100864
#define MOFF  (CKOFF + LL*4)                   // 102400
#define SMEM_ATTN (MOFF + LL*4)                // 103936

__global__ void __launch_bounds__(256) attn_fused(
    const int* __restrict__ mask, float* __restrict__ attn)
{
    extern __shared__ char smraw[];
    float*  E  = (float*) (smraw + EOFF);   // [32][LLP]
    __half* FQ = (__half*)(smraw + FQOFF);  // [32][FDP]
    __half* FK = (__half*)(smraw + FKOFF);  // [64][FDP]
    __half* Vh = (__half*)(smraw + VHOFF);  // [64][VHS]
    float*  CK = (float*) (smraw + CKOFF);
    int*    M  = (int*)   (smraw + MOFF);

    int tid = threadIdx.x;
    int lane = tid & 31, warp = tid >> 5;
    int wm = (warp & 1) * 16;
    int wn = (warp >> 1) * 16;
    int gr = lane >> 2, tg = lane & 3;
    int bh = blockIdx.y, b = bh >> 3, h = bh & 7;
    int q0 = blockIdx.x * 32;

    for (int j = tid; j < LL; j += 256) { M[j] = mask[b * LL + j]; CK[j] = g_ck[bh * LL + j]; }
    {
        const unsigned* s32 = (const unsigned*)(g_FQ + (size_t)(bh * LL + q0) * FD);
#pragma unroll
        for (int i = 0; i < 16; i++) {
            int idx = tid + i * 256;
            int r = idx >> 7, c2 = idx & 127;
            *(unsigned*)&FQ[r * FDP + c2 * 2] = s32[r * 128 + c2];
        }
    }

    for (int c = 0; c < 6; c++) {
        __syncthreads();
        {
            const unsigned* s32 = (const unsigned*)(g_FK + (size_t)(bh * LL + c * 64) * FD);
#pragma unroll
            for (int i = 0; i < 32; i++) {
                int idx = tid + i * 256;
                int r = idx >> 7, c2 = idx & 127;
                *(unsigned*)&FK[r * FDP + c2 * 2] = s32[r * 128 + c2];
            }
        }
        __syncthreads();
        float eacc[2][4];
#pragma unroll
        for (int nt = 0; nt < 2; nt++)
#pragma unroll
            for (int i = 0; i < 4; i++) eacc[nt][i] = 0.f;
#pragma unroll
        for (int ks = 0; ks < 16; ks++) {
            int k0 = ks * 16;
            unsigned a[4], bf[2][2];
            a[0] = *(const unsigned*)&FQ[(wm + gr    ) * FDP + k0 + 2 * tg];
            a[1] = *(const unsigned*)&FQ[(wm + gr + 8) * FDP + k0 + 2 * tg];
            a[2] = *(const unsigned*)&FQ[(wm + gr    ) * FDP + k0 + 2 * tg + 8];
            a[3] = *(const unsigned*)&FQ[(wm + gr + 8) * FDP + k0 + 2 * tg + 8];
#pragma unroll
            for (int nt = 0; nt < 2; nt++) {
                int rn = wn + nt * 8 + gr;
                bf[nt][0] = *(const unsigned*)&FK[rn * FDP + k0 + 2 * tg];
                bf[nt][1] = *(const unsigned*)&FK[rn * FDP + k0 + 2 * tg + 8];
            }
            mma_f16(eacc[0], a, bf[0]);
            mma_f16(eacc[1], a, bf[1]);
        }
#pragma unroll
        for (int nt = 0; nt < 2; nt++) {
            int col = c * 64 + wn + nt * 8 + 2 * tg;
            *(float2*)&E[(wm + gr    ) * LLP + col] = make_float2(eacc[nt][0], eacc[nt][1]);
            *(float2*)&E[(wm + gr + 8) * LLP + col] = make_float2(eacc[nt][2], eacc[nt][3]);
        }
    }
    __syncthreads();

    {
        int row = tid >> 3, lx = tid & 7;
        float mx = -3.0e38f;
        for (int i = 0; i < 48; i++) {
            int j = lx + i * 8;
            float e = E[row * LLP + j] + CK[j];
            if (M[j] == 0) e = -1e10f;
            E[row * LLP + j] = e;
            mx = fmaxf(mx, e);
        }
#pragma unroll
        for (int o = 4; o > 0; o >>= 1) mx = fmaxf(mx, __shfl_xor_sync(0xffffffffu, mx, o));
        float sum = 0.f;
        for (int i = 0; i < 48; i++) {
            int j = lx + i * 8;
            float p = __expf(E[row * LLP + j] - mx);
            sum += p;
            E[row * LLP + j] = p;
        }
#pragma unroll
        for (int o = 4; o > 0; o >>= 1) sum += __shfl_xor_sync(0xffffffffu, sum, o);
        float inv = __frcp_rn(sum);
        for (int i = 0; i < 48; i++) E[row * LLP + lx + i * 8] *= inv;
    }
    __syncthreads();

    {
        float* dst = attn + (size_t)(bh * LL + q0) * LL;
        for (int idx = tid; idx < 32 * LL; idx += 256) {
            int r = idx / LL, j = idx - r * LL;
            dst[r * LL + j] = E[r * LLP + j];
        }
    }

    float xacc[2][4];
#pragma unroll
    for (int nt = 0; nt < 2; nt++)
#pragma unroll
        for (int i = 0; i < 4; i++) xacc[nt][i] = 0.f;

    for (int c = 0; c < 6; c++) {
        __syncthreads();
        {
            const unsigned* s32 = (const unsigned*)(g_Vh + (size_t)bh * DD * LL + c * 64);
#pragma unroll
            for (int i = 0; i < 8; i++) {
                int idx = tid + i * 256;
                int d = idx >> 5, c2 = idx & 31;
                *(unsigned*)&Vh[d * VHS + c2 * 2] = s32[d * (LL / 2) + c2];
            }
        }
        __syncthreads();
#pragma unroll
        for (int ks = 0; ks < 4; ks++) {
            int kg = c * 64 + ks * 16;
            unsigned a[4], bf[2][2];
            float2 p0 = *(const float2*)&E[(wm + gr    ) * LLP + kg + 2 * tg];
            float2 p1 = *(const float2*)&E[(wm + gr + 8) * LLP + kg + 2 * tg];
            float2 p2 = *(const float2*)&E[(wm + gr    ) * LLP + kg + 2 * tg + 8];
            float2 p3 = *(const float2*)&E[(wm + gr + 8) * LLP + kg + 2 * tg + 8];
            a[0] = h2u(__floats2half2_rn(p0.x, p0.y));
            a[1] = h2u(__floats2half2_rn(p1.x, p1.y));
            a[2] = h2u(__floats2half2_rn(p2.x, p2.y));
            a[3] = h2u(__floats2half2_rn(p3.x, p3.y));
            int kl = ks * 16 + 2 * tg;
#pragma unroll
            for (int nt = 0; nt < 2; nt++) {
                int rn = wn + nt * 8 + gr;
                bf[nt][0] = *(const unsigned*)&Vh[rn * VHS + kl];
                bf[nt][1] = *(const unsigned*)&Vh[rn * VHS + kl + 8];
            }
            mma_f16(xacc[0], a, bf[0]);
            mma_f16(xacc[1], a, bf[1]);
        }
    }

    {
        int q = q0 + wm + gr;
#pragma unroll
        for (int nt = 0; nt < 2; nt++) {
            int d = h * DD + wn + nt * 8 + 2 * tg;
            *(float2*)&g_X[(size_t)(b * LL + q    ) * HIDN + d] = make_float2(xacc[nt][0], xacc[nt][1]);
            *(float2*)&g_X[(size_t)(b * LL + q + 8) * HIDN + d] = make_float2(xacc[nt][2], xacc[nt][3]);
        }
    }
}

extern "C" void kernel_launch(void* const* d_in, const int* in_sizes, int n_in,
                              void* d_out, int out_size)
{
    const float* query = (const float*)d_in[0];
    const float* key_  = (const float*)d_in[1];
    const float* value = (const float*)d_in[2];
    const int*   mask  = (const int*)  d_in[3];
    const float* Wq = (const float*)d_in[4];
    const float* bq = (const float*)d_in[5];
    const float* Wk = (const float*)d_in[6];
    const float* bk = (const float*)d_in[7];
    const float* Wv = (const float*)d_in[8];
    const float* bv = (const float*)d_in[9];
    const float* Wo = (const float*)d_in[10];
    const float* bo = (const float*)d_in[11];
    const float* W1 = (const float*)d_in[12];
    const float* b1 = (const float*)d_in[13];
    const float* W2 = (const float*)d_in[14];
    const float* b2 = (const float*)d_in[15];
    const float* vw = (const float*)d_in[16];
    (void)d_in[17];
    (void)in_sizes; (void)n_in;

    float* out = (float*)d_out;

    float *gX, *gA, *gWfq, *gWfk, *gbfq, *gbfk;
    cudaGetSymbolAddress((void**)&gX,   g_X);
    cudaGetSymbolAddress((void**)&gA,   g_attn);
    cudaGetSymbolAddress((void**)&gWfq, g_Wfq);
    cudaGetSymbolAddress((void**)&gWfk, g_Wfk);
    cudaGetSymbolAddress((void**)&gbfq, g_bfq);
    cudaGetSymbolAddress((void**)&gbfk, g_bfk);

    float* attn_dst = (out_size >= X_ELEMS + A_ELEMS) ? (out + X_ELEMS) : gA;

    cudaFuncSetAttribute(attn_fused, cudaFuncAttributeMaxDynamicSharedMemorySize, SMEM_ATTN);

    // 1) fuse W1@Wq and W2@Wk (128 blocks)
    prep_fuse<<<dim3(HH, 2, HIDN / 64), 256>>>(W1, b1, W2, b2, Wq, bq, Wk, bk);

    // 2) projections + featurization — tf32 TC BK=64, 288 blocks (BM=64)
    gemm_tc<64><<<dim3(HIDN / 64, MROWS / 64, 3), 256>>>(
        query, gWfq, gbfq, nullptr, 3,
        key_,  gWfk, gbfk, nullptr, 4,
        value, Wv,   bv,   nullptr, 5,
        vw);

    // 3) attention: E-mma + softmax + AV-mma (192 blocks, dyn smem)
    attn_fused<<<dim3(LL / 32, BH), 256, SMEM_ATTN>>>(mask, attn_dst);

    // 4) output projection — tf32 TC BK=64, 192 blocks (BM=32)
    gemm_tc<32><<<dim3(HIDN / 64, MROWS / 32, 1), 256>>>(
        gX, Wo, bo, out, 0,
        gX, Wo, bo, out, 0,
        gX, Wo, bo, out, 0,
        vw);
}

// round 14
// speedup vs baseline: 1.2181x; 1.1230x over previous
#include <cuda_runtime.h>
#include <cuda_fp16.h>

#define BB 2
#define LL 384
#define HH 8
#define DD 64
#define HIDN 512
#define BH (BB*HH)          // 16
#define MROWS (BB*LL)       // 768
#define X_ELEMS (MROWS*HIDN)    // 393216
#define A_ELEMS (BH*LL*LL)      // 2359296
#define FD 256              // feature dim (4 segments x 64)

// -------- scratch (no dynamic allocation allowed) --------
__device__ __half g_FQ[BH*LL*FD];   // [bh][l][256]  q-side features
__device__ __half g_FK[BH*LL*FD];   // [bh][l][256]  k-side features
__device__ __half g_Vh[BH*DD*LL];   // [bh][d][l]    V transposed, half
__device__ float  g_ck[BH*LL];      // per-k energy constant
__device__ float  g_X [X_ELEMS];
__device__ float  g_attn[A_ELEMS];
__device__ float  g_Wfq[HIDN*HIDN];
__device__ float  g_Wfk[HIDN*HIDN];
__device__ float  g_bfq[HIDN];
__device__ float  g_bfk[HIDN];

__device__ __forceinline__ float tanh_ap(float x) {
    float y; asm("tanh.approx.f32 %0, %1;" : "=f"(y) : "f"(x)); return y;
}
__device__ __forceinline__ void mma_f16(float* c, const unsigned* a, const unsigned* b) {
    asm volatile(
        "mma.sync.aligned.m16n8k16.row.col.f32.f16.f16.f32 "
        "{%0,%1,%2,%3}, {%4,%5,%6,%7}, {%8,%9}, {%0,%1,%2,%3};"
        : "+f"(c[0]), "+f"(c[1]), "+f"(c[2]), "+f"(c[3])
        : "r"(a[0]), "r"(a[1]), "r"(a[2]), "r"(a[3]), "r"(b[0]), "r"(b[1]));
}
__device__ __forceinline__ unsigned h2u(__half2 v) { return *(unsigned*)&v; }

// ---------------- prep: fused per-head weights ----------------
__global__ void __launch_bounds__(256) prep_fuse(
    const float* __restrict__ W1, const float* __restrict__ b1,
    const float* __restrict__ W2, const float* __restrict__ b2,
    const float* __restrict__ Wq, const float* __restrict__ bq,
    const float* __restrict__ Wk, const float* __restrict__ bk)
{
    int h   = blockIdx.x;
    int sel = blockIdx.y;
    int c0  = blockIdx.z * 64;
    const float* Wh   = sel ? W2 : W1;
    const float* bh_  = sel ? b2 : b1;
    const float* Wsrc = sel ? Wk : Wq;
    const float* bsrc = sel ? bk : bq;
    float* Wout = sel ? g_Wfk : g_Wfq;
    float* bout = sel ? g_bfk : g_bfq;
    __shared__ float Ws[DD][DD + 1];
    __shared__ float Ts[DD][DD + 1];
    int tid = threadIdx.x;
    for (int t = tid; t < DD * DD; t += 256) {
        Ws[t >> 6][t & 63] = Wh[t];
        Ts[t >> 6][t & 63] = Wsrc[(h * DD + (t >> 6)) * HIDN + c0 + (t & 63)];
    }
    __syncthreads();
    if (blockIdx.z == 0 && tid < DD) {
        float acc = bh_[tid];
        for (int j = 0; j < DD; j++) acc += Ws[tid][j] * bsrc[h * DD + j];
        bout[h * DD + tid] = acc;
    }
    int i = tid & 63;
    int g = tid >> 6;
#pragma unroll
    for (int cc = 0; cc < 16; cc++) {
        int c = g * 16 + cc;
        float acc = 0.f;
#pragma unroll 8
        for (int j = 0; j < DD; j++) acc = fmaf(Ws[i][j], Ts[j][c], acc);
        Wout[(h * DD + i) * HIDN + c0 + c] = acc;
    }
}

// ---------------- f16 TC GEMM v5: BK=64, m16n8k16, f32 accum ----------------
// BM=64: 8 warps as 4m x 2n (warp 16x32). BM=32: 8 warps as 2m x 4n (warp 16x16).
// Staging: half2 words, row stride 36 words (72 halves) -> conflict-free frags.
// mode 0: plain fp32 [m, HIDN]; mode 3: Q-featurize; mode 4: K-featurize+ck; mode 5: V->half [d][l]
template<int BM>
__global__ void __launch_bounds__(256) gemm_tc(
    const float* __restrict__ X0, const float* __restrict__ Wm0, const float* __restrict__ B0, float* __restrict__ O0, int md0,
    const float* __restrict__ X1, const float* __restrict__ Wm1, const float* __restrict__ B1, float* __restrict__ O1, int md1,
    const float* __restrict__ X2, const float* __restrict__ Wm2, const float* __restrict__ B2, float* __restrict__ O2, int md2,
    const float* __restrict__ vw)
{
    const int BK = 64;
    const int NIT = HIDN / BK;        // 8
    const int NT = (BM == 64) ? 4 : 2;
    const int NLX = BM / 16;          // float4 X loads per thread (4 or 2)
    int z = blockIdx.z;
    const float* X  = z == 0 ? X0  : (z == 1 ? X1  : X2);
    const float* W  = z == 0 ? Wm0 : (z == 1 ? Wm1 : Wm2);
    const float* Bi = z == 0 ? B0  : (z == 1 ? B1  : B2);
    float*       O  = z == 0 ? O0  : (z == 1 ? O1  : O2);
    int        mode = z == 0 ? md0 : (z == 1 ? md1 : md2);

    __shared__ union {
        struct { unsigned X[BM * 36]; unsigned W[64 * 36]; } st;  // half2 words
        float out[BM * 68];
    } sm;

    int tid = threadIdx.x;
    int lane = tid & 31;
    int warp = tid >> 5;
    int warp_m = (BM == 64) ? (warp & 3) * 16 : (warp & 1) * 16;
    int warp_n = (BM == 64) ? (warp >> 2) * 32 : (warp >> 1) * 16;
    int gr = lane >> 2;
    int tg = lane & 3;
    int m0 = blockIdx.y * BM, n0 = blockIdx.x * 64;

    float acc[NT][4];
#pragma unroll
    for (int nt = 0; nt < NT; nt++)
#pragma unroll
        for (int i = 0; i < 4; i++) acc[nt][i] = 0.f;

    // prefetch tile 0 (full 64-wide K slab)
    float4 px[NLX], pw[4];
#pragma unroll
    for (int i = 0; i < NLX; i++) {
        int idx = tid + i * 256;
        int r = idx >> 4, c4 = idx & 15;
        px[i] = *(const float4*)&X[(m0 + r) * HIDN + c4 * 4];
    }
#pragma unroll
    for (int i = 0; i < 4; i++) {
        int idx = tid + i * 256;
        int r = idx >> 4, c4 = idx & 15;
        pw[i] = *(const float4*)&W[(n0 + r) * HIDN + c4 * 4];
    }

    for (int it = 0; it < NIT; it++) {
        // stage prefetched tile (fp32 -> half2, RN)
#pragma unroll
        for (int i = 0; i < NLX; i++) {
            int idx = tid + i * 256;
            int r = idx >> 4, c4 = idx & 15;
            uint2 u;
            u.x = h2u(__floats2half2_rn(px[i].x, px[i].y));
            u.y = h2u(__floats2half2_rn(px[i].z, px[i].w));
            *(uint2*)&sm.st.X[r * 36 + c4 * 2] = u;
        }
#pragma unroll
        for (int i = 0; i < 4; i++) {
            int idx = tid + i * 256;
            int r = idx >> 4, c4 = idx & 15;
            uint2 u;
            u.x = h2u(__floats2half2_rn(pw[i].x, pw[i].y));
            u.y = h2u(__floats2half2_rn(pw[i].z, pw[i].w));
            *(uint2*)&sm.st.W[r * 36 + c4 * 2] = u;
        }
        __syncthreads();
        // prefetch next slab while MMAs run
        if (it + 1 < NIT) {
            int kk = (it + 1) * BK;
#pragma unroll
            for (int i = 0; i < NLX; i++) {
                int idx = tid + i * 256;
                int r = idx >> 4, c4 = idx & 15;
                px[i] = *(const float4*)&X[(m0 + r) * HIDN + kk + c4 * 4];
            }
#pragma unroll
            for (int i = 0; i < 4; i++) {
                int idx = tid + i * 256;
                int r = idx >> 4, c4 = idx & 15;
                pw[i] = *(const float4*)&W[(n0 + r) * HIDN + kk + c4 * 4];
            }
        }
        // 4 k16-steps per 64-wide slab
#pragma unroll
        for (int s = 0; s < 4; s++) {
            int kb = s * 8;   // half2-word offset
            unsigned a[4], b[NT][2];
            a[0] = sm.st.X[(warp_m + gr    ) * 36 + kb + tg];
            a[1] = sm.st.X[(warp_m + gr + 8) * 36 + kb + tg];
            a[2] = sm.st.X[(warp_m + gr    ) * 36 + kb + 4 + tg];
            a[3] = sm.st.X[(warp_m + gr + 8) * 36 + kb + 4 + tg];
#pragma unroll
            for (int nt = 0; nt < NT; nt++) {
                int rn = warp_n + nt * 8 + gr;
                b[nt][0] = sm.st.W[rn * 36 + kb + tg];
                b[nt][1] = sm.st.W[rn * 36 + kb + 4 + tg];
            }
#pragma unroll
            for (int nt = 0; nt < NT; nt++)
                mma_f16(acc[nt], a, b[nt]);
        }
        __syncthreads();
    }

    // epilogue: acc -> smem tile (overlays staging buffers)
#pragma unroll
    for (int nt = 0; nt < NT; nt++) {
        int col = warp_n + nt * 8 + 2 * tg;
        sm.out[(warp_m + gr    ) * 68 + col    ] = acc[nt][0];
        sm.out[(warp_m + gr    ) * 68 + col + 1] = acc[nt][1];
        sm.out[(warp_m + gr + 8) * 68 + col    ] = acc[nt][2];
        sm.out[(warp_m + gr + 8) * 68 + col + 1] = acc[nt][3];
    }
    __syncthreads();

    int b_ = m0 / LL, l0 = m0 - b_ * LL;
    int h = n0 >> 6;
    int bh = b_ * HH + h;

    if (mode == 0) {
#pragma unroll
        for (int i = 0; i < BM / 16; i++) {
            int idx = tid + i * 256;
            int r = idx >> 4, c4 = idx & 15;
            float4 v = *(float4*)&sm.out[r * 68 + c4 * 4];
            float4 b4 = *(const float4*)&Bi[n0 + c4 * 4];
            v.x += b4.x; v.y += b4.y; v.z += b4.z; v.w += b4.w;
            *(float4*)&O[(m0 + r) * HIDN + n0 + c4 * 4] = v;
        }
    } else if (mode == 3 || mode == 4) {
        __half* Fdst = (mode == 3 ? g_FQ : g_FK) + (size_t)(bh * LL + l0) * FD;
#pragma unroll
        for (int i = 0; i < BM / 16; i++) {
            int idx = tid + i * 256;
            int r = idx >> 4, c4 = idx & 15;
            int d0 = c4 * 4;
            float4 v = *(float4*)&sm.out[r * 68 + d0];
            float4 b4 = *(const float4*)&Bi[n0 + d0];
            float t0 = tanh_ap(v.x + b4.x), t1 = tanh_ap(v.y + b4.y);
            float t2 = tanh_ap(v.z + b4.z), t3 = tanh_ap(v.w + b4.w);
            float w0 = __ldg(&vw[d0]), w1 = __ldg(&vw[d0 + 1]);
            float w2 = __ldg(&vw[d0 + 2]), w3 = __ldg(&vw[d0 + 3]);
            __half* row = Fdst + (size_t)r * FD;
            if (mode == 3) {
                // FQ = [ta^2, vw*ta, ta^3, vw*ta^2]
                *(__half2*)&row[0*64 + d0    ] = __floats2half2_rn(t0*t0, t1*t1);
                *(__half2*)&row[0*64 + d0 + 2] = __floats2half2_rn(t2*t2, t3*t3);
                *(__half2*)&row[1*64 + d0    ] = __floats2half2_rn(w0*t0, w1*t1);
                *(__half2*)&row[1*64 + d0 + 2] = __floats2half2_rn(w2*t2, w3*t3);
                *(__half2*)&row[2*64 + d0    ] = __floats2half2_rn(t0*t0*t0, t1*t1*t1);
                *(__half2*)&row[2*64 + d0 + 2] = __floats2half2_rn(t2*t2*t2, t3*t3*t3);
                *(__half2*)&row[3*64 + d0    ] = __floats2half2_rn(w0*t0*t0, w1*t1*t1);
                *(__half2*)&row[3*64 + d0 + 2] = __floats2half2_rn(w2*t2*t2, w3*t3*t3);
            } else {
                // FK = [-vw*tb, -tb^2, vw*tb^2, tb^3]
                *(__half2*)&row[0*64 + d0    ] = __floats2half2_rn(-w0*t0, -w1*t1);
                *(__half2*)&row[0*64 + d0 + 2] = __floats2half2_rn(-w2*t2, -w3*t3);
                *(__half2*)&row[1*64 + d0    ] = __floats2half2_rn(-t0*t0, -t1*t1);
                *(__half2*)&row[1*64 + d0 + 2] = __floats2half2_rn(-t2*t2, -t3*t3);
                *(__half2*)&row[2*64 + d0    ] = __floats2half2_rn(w0*t0*t0, w1*t1*t1);
                *(__half2*)&row[2*64 + d0 + 2] = __floats2half2_rn(w2*t2*t2, w3*t3*t3);
                *(__half2*)&row[3*64 + d0    ] = __floats2half2_rn(t0*t0*t0, t1*t1*t1);
                *(__half2*)&row[3*64 + d0 + 2] = __floats2half2_rn(t2*t2*t2, t3*t3*t3);
                float cp = w0*t0 + w1*t1 + w2*t2 + w3*t3;
#pragma unroll
                for (int o = 1; o < 16; o <<= 1) cp += __shfl_xor_sync(0xffffffffu, cp, o);
                if ((tid & 15) == 0) g_ck[bh * LL + l0 + r] = cp;
            }
        }
    } else {
        // mode 5: V -> half, transposed [bh][d][l]
        __half* base = g_Vh + (size_t)bh * DD * LL;
#pragma unroll
        for (int i = 0; i < BM / 16; i++) {
            int idx = tid + i * 256;
            int d = idx >> 4, l4 = idx & 15;
            float bd = __ldg(&Bi[n0 + d]);
            float v0 = sm.out[(l4 * 4 + 0) * 68 + d] + bd;
            float v1 = sm.out[(l4 * 4 + 1) * 68 + d] + bd;
            float v2 = sm.out[(l4 * 4 + 2) * 68 + d] + bd;
            float v3 = sm.out[(l4 * 4 + 3) * 68 + d] + bd;
            *(__half2*)&base[d * LL + l0 + l4 * 4    ] = __floats2half2_rn(v0, v1);
            *(__half2*)&base[d * LL + l0 + l4 * 4 + 2] = __floats2half2_rn(v2, v3);
        }
    }
}

// ---------------- attention: E = FQ@FK^T + ck -> softmax -> X = P@V (f16 MMA) ----
#define LLP 392
#define FDP 264
#define VHS 72
#define EOFF  0
#define UOFF  (32*LLP*4)                       // 50176
#define FQOFF UOFF
#define FKOFF (UOFF + 32*FDP*2)                // +16896
#define VHOFF UOFF
#define CKOFF (UOFF + 32*FDP*2 + 64*FDP*2)     // 100864
#define MOFF  (CKOFF + LL*4)                   // 102400
#define SMEM_ATTN (MOFF + LL*4)                // 103936

__global__ void __launch_bounds__(256) attn_fused(
    const int* __restrict__ mask, float* __restrict__ attn)
{
    extern __shared__ char smraw[];
    float*  E  = (float*) (smraw + EOFF);   // [32][LLP]
    __half* FQ = (__half*)(smraw + FQOFF);  // [32][FDP]
    __half* FK = (__half*)(smraw + FKOFF);  // [64][FDP]
    __half* Vh = (__half*)(smraw + VHOFF);  // [64][VHS]
    float*  CK = (float*) (smraw + CKOFF);
    int*    M  = (int*)   (smraw + MOFF);

    int tid = threadIdx.x;
    int lane = tid & 31, warp = tid >> 5;
    int wm = (warp & 1) * 16;
    int wn = (warp >> 1) * 16;
    int gr = lane >> 2, tg = lane & 3;
    int bh = blockIdx.y, b = bh >> 3, h = bh & 7;
    int q0 = blockIdx.x * 32;

    for (int j = tid; j < LL; j += 256) { M[j] = mask[b * LL + j]; CK[j] = g_ck[bh * LL + j]; }
    {
        const unsigned* s32 = (const unsigned*)(g_FQ + (size_t)(bh * LL + q0) * FD);
#pragma unroll
        for (int i = 0; i < 16; i++) {
            int idx = tid + i * 256;
            int r = idx >> 7, c2 = idx & 127;
            *(unsigned*)&FQ[r * FDP + c2 * 2] = s32[r * 128 + c2];
        }
    }

    for (int c = 0; c < 6; c++) {
        __syncthreads();
        {
            const unsigned* s32 = (const unsigned*)(g_FK + (size_t)(bh * LL + c * 64) * FD);
#pragma unroll
            for (int i = 0; i < 32; i++) {
                int idx = tid + i * 256;
                int r = idx >> 7, c2 = idx & 127;
                *(unsigned*)&FK[r * FDP + c2 * 2] = s32[r * 128 + c2];
            }
        }
        __syncthreads();
        float eacc[2][4];
#pragma unroll
        for (int nt = 0; nt < 2; nt++)
#pragma unroll
            for (int i = 0; i < 4; i++) eacc[nt][i] = 0.f;
#pragma unroll
        for (int ks = 0; ks < 16; ks++) {
            int k0 = ks * 16;
            unsigned a[4], bf[2][2];
            a[0] = *(const unsigned*)&FQ[(wm + gr    ) * FDP + k0 + 2 * tg];
            a[1] = *(const unsigned*)&FQ[(wm + gr + 8) * FDP + k0 + 2 * tg];
            a[2] = *(const unsigned*)&FQ[(wm + gr    ) * FDP + k0 + 2 * tg + 8];
            a[3] = *(const unsigned*)&FQ[(wm + gr + 8) * FDP + k0 + 2 * tg + 8];
#pragma unroll
            for (int nt = 0; nt < 2; nt++) {
                int rn = wn + nt * 8 + gr;
                bf[nt][0] = *(const unsigned*)&FK[rn * FDP + k0 + 2 * tg];
                bf[nt][1] = *(const unsigned*)&FK[rn * FDP + k0 + 2 * tg + 8];
            }
            mma_f16(eacc[0], a, bf[0]);
            mma_f16(eacc[1], a, bf[1]);
        }
#pragma unroll
        for (int nt = 0; nt < 2; nt++) {
            int col = c * 64 + wn + nt * 8 + 2 * tg;
            *(float2*)&E[(wm + gr    ) * LLP + col] = make_float2(eacc[nt][0], eacc[nt][1]);
            *(float2*)&E[(wm + gr + 8) * LLP + col] = make_float2(eacc[nt][2], eacc[nt][3]);
        }
    }
    __syncthreads();

    {
        int row = tid >> 3, lx = tid & 7;
        float mx = -3.0e38f;
        for (int i = 0; i < 48; i++) {
            int j = lx + i * 8;
            float e = E[row * LLP + j] + CK[j];
            if (M[j] == 0) e = -1e10f;
            E[row * LLP + j] = e;
            mx = fmaxf(mx, e);
        }
#pragma unroll
        for (int o = 4; o > 0; o >>= 1) mx = fmaxf(mx, __shfl_xor_sync(0xffffffffu, mx, o));
        float sum = 0.f;
        for (int i = 0; i < 48; i++) {
            int j = lx + i * 8;
            float p = __expf(E[row * LLP + j] - mx);
            sum += p;
            E[row * LLP + j] = p;
        }
#pragma unroll
        for (int o = 4; o > 0; o >>= 1) sum += __shfl_xor_sync(0xffffffffu, sum, o);
        float inv = __frcp_rn(sum);
        for (int i = 0; i < 48; i++) E[row * LLP + lx + i * 8] *= inv;
    }
    __syncthreads();

    {
        float* dst = attn + (size_t)(bh * LL + q0) * LL;
        for (int idx = tid; idx < 32 * LL; idx += 256) {
            int r = idx / LL, j = idx - r * LL;
            dst[r * LL + j] = E[r * LLP + j];
        }
    }

    float xacc[2][4];
#pragma unroll
    for (int nt = 0; nt < 2; nt++)
#pragma unroll
        for (int i = 0; i < 4; i++) xacc[nt][i] = 0.f;

    for (int c = 0; c < 6; c++) {
        __syncthreads();
        {
            const unsigned* s32 = (const unsigned*)(g_Vh + (size_t)bh * DD * LL + c * 64);
#pragma unroll
            for (int i = 0; i < 8; i++) {
                int idx = tid + i * 256;
                int d = idx >> 5, c2 = idx & 31;
                *(unsigned*)&Vh[d * VHS + c2 * 2] = s32[d * (LL / 2) + c2];
            }
        }
        __syncthreads();
#pragma unroll
        for (int ks = 0; ks < 4; ks++) {
            int kg = c * 64 + ks * 16;
            unsigned a[4], bf[2][2];
            float2 p0 = *(const float2*)&E[(wm + gr    ) * LLP + kg + 2 * tg];
            float2 p1 = *(const float2*)&E[(wm + gr + 8) * LLP + kg + 2 * tg];
            float2 p2 = *(const float2*)&E[(wm + gr    ) * LLP + kg + 2 * tg + 8];
            float2 p3 = *(const float2*)&E[(wm + gr + 8) * LLP + kg + 2 * tg + 8];
            a[0] = h2u(__floats2half2_rn(p0.x, p0.y));
            a[1] = h2u(__floats2half2_rn(p1.x, p1.y));
            a[2] = h2u(__floats2half2_rn(p2.x, p2.y));
            a[3] = h2u(__floats2half2_rn(p3.x, p3.y));
            int kl = ks * 16 + 2 * tg;
#pragma unroll
            for (int nt = 0; nt < 2; nt++) {
                int rn = wn + nt * 8 + gr;
                bf[nt][0] = *(const unsigned*)&Vh[rn * VHS + kl];
                bf[nt][1] = *(const unsigned*)&Vh[rn * VHS + kl + 8];
            }
            mma_f16(xacc[0], a, bf[0]);
            mma_f16(xacc[1], a, bf[1]);
        }
    }

    {
        int q = q0 + wm + gr;
#pragma unroll
        for (int nt = 0; nt < 2; nt++) {
            int d = h * DD + wn + nt * 8 + 2 * tg;
            *(float2*)&g_X[(size_t)(b * LL + q    ) * HIDN + d] = make_float2(xacc[nt][0], xacc[nt][1]);
            *(float2*)&g_X[(size_t)(b * LL + q + 8) * HIDN + d] = make_float2(xacc[nt][2], xacc[nt][3]);
        }
    }
}

extern "C" void kernel_launch(void* const* d_in, const int* in_sizes, int n_in,
                              void* d_out, int out_size)
{
    const float* query = (const float*)d_in[0];
    const float* key_  = (const float*)d_in[1];
    const float* value = (const float*)d_in[2];
    const int*   mask  = (const int*)  d_in[3];
    const float* Wq = (const float*)d_in[4];
    const float* bq = (const float*)d_in[5];
    const float* Wk = (const float*)d_in[6];
    const float* bk = (const float*)d_in[7];
    const float* Wv = (const float*)d_in[8];
    const float* bv = (const float*)d_in[9];
    const float* Wo = (const float*)d_in[10];
    const float* bo = (const float*)d_in[11];
    const float* W1 = (const float*)d_in[12];
    const float* b1 = (const float*)d_in[13];
    const float* W2 = (const float*)d_in[14];
    const float* b2 = (const float*)d_in[15];
    const float* vw = (const float*)d_in[16];
    (void)d_in[17];
    (void)in_sizes; (void)n_in;

    float* out = (float*)d_out;

    float *gX, *gA, *gWfq, *gWfk, *gbfq, *gbfk;
    cudaGetSymbolAddress((void**)&gX,   g_X);
    cudaGetSymbolAddress((void**)&gA,   g_attn);
    cudaGetSymbolAddress((void**)&gWfq, g_Wfq);
    cudaGetSymbolAddress((void**)&gWfk, g_Wfk);
    cudaGetSymbolAddress((void**)&gbfq, g_bfq);
    cudaGetSymbolAddress((void**)&gbfk, g_bfk);

    float* attn_dst = (out_size >= X_ELEMS + A_ELEMS) ? (out + X_ELEMS) : gA;

    cudaFuncSetAttribute(attn_fused, cudaFuncAttributeMaxDynamicSharedMemorySize, SMEM_ATTN);

    // 1) fuse W1@Wq and W2@Wk (128 blocks)
    prep_fuse<<<dim3(HH, 2, HIDN / 64), 256>>>(W1, b1, W2, b2, Wq, bq, Wk, bk);

    // 2) projections + featurization — f16 TC BK=64, 288 blocks (BM=64)
    gemm_tc<64><<<dim3(HIDN / 64, MROWS / 64, 3), 256>>>(
        query, gWfq, gbfq, nullptr, 3,
        key_,  gWfk, gbfk, nullptr, 4,
        value, Wv,   bv,   nullptr, 5,
        vw);

    // 3) attention: E-mma + softmax + AV-mma (192 blocks, dyn smem)
    attn_fused<<<dim3(LL / 32, BH), 256, SMEM_ATTN>>>(mask, attn_dst);

    // 4) output projection — f16 TC BK=64, 192 blocks (BM=32)
    gemm_tc<32><<<dim3(HIDN / 64, MROWS / 32, 1), 256>>>(
        gX, Wo, bo, out, 0,
        gX, Wo, bo, out, 0,
        gX, Wo, bo, out, 0,
        vw);
}

// round 15
// speedup vs baseline: 1.2875x; 1.0570x over previous
#include <cuda_runtime.h>
#include <cuda_fp16.h>

#define BB 2
#define LL 384
#define HH 8
#define DD 64
#define HIDN 512
#define BH (BB*HH)          // 16
#define MROWS (BB*LL)       // 768
#define X_ELEMS (MROWS*HIDN)    // 393216
#define A_ELEMS (BH*LL*LL)      // 2359296
#define FD 256              // feature dim (4 segments x 64)

// -------- scratch (no dynamic allocation allowed) --------
__device__ __half g_FQ[BH*LL*FD];   // [bh][l][256]  q-side features
__device__ __half g_FK[BH*LL*FD];   // [bh][l][256]  k-side features
__device__ __half g_Vh[BH*DD*LL];   // [bh][d][l]    V transposed, half
__device__ float  g_ck[BH*LL];      // per-k energy constant
__device__ float  g_X [X_ELEMS];
__device__ float  g_attn[A_ELEMS];
__device__ float  g_Wfq[HIDN*HIDN];
__device__ float  g_Wfk[HIDN*HIDN];
__device__ float  g_bfq[HIDN];
__device__ float  g_bfk[HIDN];

__device__ __forceinline__ float tanh_ap(float x) {
    float y; asm("tanh.approx.f32 %0, %1;" : "=f"(y) : "f"(x)); return y;
}
__device__ __forceinline__ void mma_f16(float* c, const unsigned* a, const unsigned* b) {
    asm volatile(
        "mma.sync.aligned.m16n8k16.row.col.f32.f16.f16.f32 "
        "{%0,%1,%2,%3}, {%4,%5,%6,%7}, {%8,%9}, {%0,%1,%2,%3};"
        : "+f"(c[0]), "+f"(c[1]), "+f"(c[2]), "+f"(c[3])
        : "r"(a[0]), "r"(a[1]), "r"(a[2]), "r"(a[3]), "r"(b[0]), "r"(b[1]));
}
__device__ __forceinline__ unsigned h2u(__half2 v) { return *(unsigned*)&v; }

// ---------------- prep: fused per-head weights ----------------
__global__ void __launch_bounds__(256) prep_fuse(
    const float* __restrict__ W1, const float* __restrict__ b1,
    const float* __restrict__ W2, const float* __restrict__ b2,
    const float* __restrict__ Wq, const float* __restrict__ bq,
    const float* __restrict__ Wk, const float* __restrict__ bk)
{
    int h   = blockIdx.x;
    int sel = blockIdx.y;
    int c0  = blockIdx.z * 64;
    const float* Wh   = sel ? W2 : W1;
    const float* bh_  = sel ? b2 : b1;
    const float* Wsrc = sel ? Wk : Wq;
    const float* bsrc = sel ? bk : bq;
    float* Wout = sel ? g_Wfk : g_Wfq;
    float* bout = sel ? g_bfk : g_bfq;
    __shared__ float Ws[DD][DD + 1];
    __shared__ float Ts[DD][DD + 1];
    int tid = threadIdx.x;
    for (int t = tid; t < DD * DD; t += 256) {
        Ws[t >> 6][t & 63] = Wh[t];
        Ts[t >> 6][t & 63] = Wsrc[(h * DD + (t >> 6)) * HIDN + c0 + (t & 63)];
    }
    __syncthreads();
    if (blockIdx.z == 0 && tid < DD) {
        float acc = bh_[tid];
        for (int j = 0; j < DD; j++) acc += Ws[tid][j] * bsrc[h * DD + j];
        bout[h * DD + tid] = acc;
    }
    int i = tid & 63;
    int g = tid >> 6;
#pragma unroll
    for (int cc = 0; cc < 16; cc++) {
        int c = g * 16 + cc;
        float acc = 0.f;
#pragma unroll 8
        for (int j = 0; j < DD; j++) acc = fmaf(Ws[i][j], Ts[j][c], acc);
        Wout[(h * DD + i) * HIDN + c0 + c] = acc;
    }
}

// ---------------- f16 TC GEMM v5: BK=64, m16n8k16, f32 accum ----------------
template<int BM>
__global__ void __launch_bounds__(256) gemm_tc(
    const float* __restrict__ X0, const float* __restrict__ Wm0, const float* __restrict__ B0, float* __restrict__ O0, int md0,
    const float* __restrict__ X1, const float* __restrict__ Wm1, const float* __restrict__ B1, float* __restrict__ O1, int md1,
    const float* __restrict__ X2, const float* __restrict__ Wm2, const float* __restrict__ B2, float* __restrict__ O2, int md2,
    const float* __restrict__ vw)
{
    const int BK = 64;
    const int NIT = HIDN / BK;        // 8
    const int NT = (BM == 64) ? 4 : 2;
    const int NLX = BM / 16;
    int z = blockIdx.z;
    const float* X  = z == 0 ? X0  : (z == 1 ? X1  : X2);
    const float* W  = z == 0 ? Wm0 : (z == 1 ? Wm1 : Wm2);
    const float* Bi = z == 0 ? B0  : (z == 1 ? B1  : B2);
    float*       O  = z == 0 ? O0  : (z == 1 ? O1  : O2);
    int        mode = z == 0 ? md0 : (z == 1 ? md1 : md2);

    __shared__ union {
        struct { unsigned X[BM * 36]; unsigned W[64 * 36]; } st;
        float out[BM * 68];
    } sm;

    int tid = threadIdx.x;
    int lane = tid & 31;
    int warp = tid >> 5;
    int warp_m = (BM == 64) ? (warp & 3) * 16 : (warp & 1) * 16;
    int warp_n = (BM == 64) ? (warp >> 2) * 32 : (warp >> 1) * 16;
    int gr = lane >> 2;
    int tg = lane & 3;
    int m0 = blockIdx.y * BM, n0 = blockIdx.x * 64;

    float acc[NT][4];
#pragma unroll
    for (int nt = 0; nt < NT; nt++)
#pragma unroll
        for (int i = 0; i < 4; i++) acc[nt][i] = 0.f;

    float4 px[NLX], pw[4];
#pragma unroll
    for (int i = 0; i < NLX; i++) {
        int idx = tid + i * 256;
        int r = idx >> 4, c4 = idx & 15;
        px[i] = *(const float4*)&X[(m0 + r) * HIDN + c4 * 4];
    }
#pragma unroll
    for (int i = 0; i < 4; i++) {
        int idx = tid + i * 256;
        int r = idx >> 4, c4 = idx & 15;
        pw[i] = *(const float4*)&W[(n0 + r) * HIDN + c4 * 4];
    }

    for (int it = 0; it < NIT; it++) {
#pragma unroll
        for (int i = 0; i < NLX; i++) {
            int idx = tid + i * 256;
            int r = idx >> 4, c4 = idx & 15;
            uint2 u;
            u.x = h2u(__floats2half2_rn(px[i].x, px[i].y));
            u.y = h2u(__floats2half2_rn(px[i].z, px[i].w));
            *(uint2*)&sm.st.X[r * 36 + c4 * 2] = u;
        }
#pragma unroll
        for (int i = 0; i < 4; i++) {
            int idx = tid + i * 256;
            int r = idx >> 4, c4 = idx & 15;
            uint2 u;
            u.x = h2u(__floats2half2_rn(pw[i].x, pw[i].y));
            u.y = h2u(__floats2half2_rn(pw[i].z, pw[i].w));
            *(uint2*)&sm.st.W[r * 36 + c4 * 2] = u;
        }
        __syncthreads();
        if (it + 1 < NIT) {
            int kk = (it + 1) * BK;
#pragma unroll
            for (int i = 0; i < NLX; i++) {
                int idx = tid + i * 256;
                int r = idx >> 4, c4 = idx & 15;
                px[i] = *(const float4*)&X[(m0 + r) * HIDN + kk + c4 * 4];
            }
#pragma unroll
            for (int i = 0; i < 4; i++) {
                int idx = tid + i * 256;
                int r = idx >> 4, c4 = idx & 15;
                pw[i] = *(const float4*)&W[(n0 + r) * HIDN + kk + c4 * 4];
            }
        }
#pragma unroll
        for (int s = 0; s < 4; s++) {
            int kb = s * 8;
            unsigned a[4], b[NT][2];
            a[0] = sm.st.X[(warp_m + gr    ) * 36 + kb + tg];
            a[1] = sm.st.X[(warp_m + gr + 8) * 36 + kb + tg];
            a[2] = sm.st.X[(warp_m + gr    ) * 36 + kb + 4 + tg];
            a[3] = sm.st.X[(warp_m + gr + 8) * 36 + kb + 4 + tg];
#pragma unroll
            for (int nt = 0; nt < NT; nt++) {
                int rn = warp_n + nt * 8 + gr;
                b[nt][0] = sm.st.W[rn * 36 + kb + tg];
                b[nt][1] = sm.st.W[rn * 36 + kb + 4 + tg];
            }
#pragma unroll
            for (int nt = 0; nt < NT; nt++)
                mma_f16(acc[nt], a, b[nt]);
        }
        __syncthreads();
    }

#pragma unroll
    for (int nt = 0; nt < NT; nt++) {
        int col = warp_n + nt * 8 + 2 * tg;
        sm.out[(warp_m + gr    ) * 68 + col    ] = acc[nt][0];
        sm.out[(warp_m + gr    ) * 68 + col + 1] = acc[nt][1];
        sm.out[(warp_m + gr + 8) * 68 + col    ] = acc[nt][2];
        sm.out[(warp_m + gr + 8) * 68 + col + 1] = acc[nt][3];
    }
    __syncthreads();

    int b_ = m0 / LL, l0 = m0 - b_ * LL;
    int h = n0 >> 6;
    int bh = b_ * HH + h;

    if (mode == 0) {
#pragma unroll
        for (int i = 0; i < BM / 16; i++) {
            int idx = tid + i * 256;
            int r = idx >> 4, c4 = idx & 15;
            float4 v = *(float4*)&sm.out[r * 68 + c4 * 4];
            float4 b4 = *(const float4*)&Bi[n0 + c4 * 4];
            v.x += b4.x; v.y += b4.y; v.z += b4.z; v.w += b4.w;
            *(float4*)&O[(m0 + r) * HIDN + n0 + c4 * 4] = v;
        }
    } else if (mode == 3 || mode == 4) {
        __half* Fdst = (mode == 3 ? g_FQ : g_FK) + (size_t)(bh * LL + l0) * FD;
#pragma unroll
        for (int i = 0; i < BM / 16; i++) {
            int idx = tid + i * 256;
            int r = idx >> 4, c4 = idx & 15;
            int d0 = c4 * 4;
            float4 v = *(float4*)&sm.out[r * 68 + d0];
            float4 b4 = *(const float4*)&Bi[n0 + d0];
            float t0 = tanh_ap(v.x + b4.x), t1 = tanh_ap(v.y + b4.y);
            float t2 = tanh_ap(v.z + b4.z), t3 = tanh_ap(v.w + b4.w);
            float w0 = __ldg(&vw[d0]), w1 = __ldg(&vw[d0 + 1]);
            float w2 = __ldg(&vw[d0 + 2]), w3 = __ldg(&vw[d0 + 3]);
            __half* row = Fdst + (size_t)r * FD;
            if (mode == 3) {
                *(__half2*)&row[0*64 + d0    ] = __floats2half2_rn(t0*t0, t1*t1);
                *(__half2*)&row[0*64 + d0 + 2] = __floats2half2_rn(t2*t2, t3*t3);
                *(__half2*)&row[1*64 + d0    ] = __floats2half2_rn(w0*t0, w1*t1);
                *(__half2*)&row[1*64 + d0 + 2] = __floats2half2_rn(w2*t2, w3*t3);
                *(__half2*)&row[2*64 + d0    ] = __floats2half2_rn(t0*t0*t0, t1*t1*t1);
                *(__half2*)&row[2*64 + d0 + 2] = __floats2half2_rn(t2*t2*t2, t3*t3*t3);
                *(__half2*)&row[3*64 + d0    ] = __floats2half2_rn(w0*t0*t0, w1*t1*t1);
                *(__half2*)&row[3*64 + d0 + 2] = __floats2half2_rn(w2*t2*t2, w3*t3*t3);
            } else {
                *(__half2*)&row[0*64 + d0    ] = __floats2half2_rn(-w0*t0, -w1*t1);
                *(__half2*)&row[0*64 + d0 + 2] = __floats2half2_rn(-w2*t2, -w3*t3);
                *(__half2*)&row[1*64 + d0    ] = __floats2half2_rn(-t0*t0, -t1*t1);
                *(__half2*)&row[1*64 + d0 + 2] = __floats2half2_rn(-t2*t2, -t3*t3);
                *(__half2*)&row[2*64 + d0    ] = __floats2half2_rn(w0*t0*t0, w1*t1*t1);
                *(__half2*)&row[2*64 + d0 + 2] = __floats2half2_rn(w2*t2*t2, w3*t3*t3);
                *(__half2*)&row[3*64 + d0    ] = __floats2half2_rn(t0*t0*t0, t1*t1*t1);
                *(__half2*)&row[3*64 + d0 + 2] = __floats2half2_rn(t2*t2*t2, t3*t3*t3);
                float cp = w0*t0 + w1*t1 + w2*t2 + w3*t3;
#pragma unroll
                for (int o = 1; o < 16; o <<= 1) cp += __shfl_xor_sync(0xffffffffu, cp, o);
                if ((tid & 15) == 0) g_ck[bh * LL + l0 + r] = cp;
            }
        }
    } else {
        __half* base = g_Vh + (size_t)bh * DD * LL;
#pragma unroll
        for (int i = 0; i < BM / 16; i++) {
            int idx = tid + i * 256;
            int d = idx >> 4, l4 = idx & 15;
            float bd = __ldg(&Bi[n0 + d]);
            float v0 = sm.out[(l4 * 4 + 0) * 68 + d] + bd;
            float v1 = sm.out[(l4 * 4 + 1) * 68 + d] + bd;
            float v2 = sm.out[(l4 * 4 + 2) * 68 + d] + bd;
            float v3 = sm.out[(l4 * 4 + 3) * 68 + d] + bd;
            *(__half2*)&base[d * LL + l0 + l4 * 4    ] = __floats2half2_rn(v0, v1);
            *(__half2*)&base[d * LL + l0 + l4 * 4 + 2] = __floats2half2_rn(v2, v3);
        }
    }
}

// ---------------- attention: E = FQ@FK^T + ck -> softmax -> X = P@V (f16 MMA) ----
// v2: register double-buffered FK / Vh chunk loads (uint4), overlapping gmem latency with MMA.
#define LLP 392
#define FDP 264
#define VHS 72
#define EOFF  0
#define UOFF  (32*LLP*4)                       // 50176
#define FQOFF UOFF
#define FKOFF (UOFF + 32*FDP*2)                // +16896
#define VHOFF UOFF
#define CKOFF (UOFF + 32*FDP*2 + 64*FDP*2)     // 100864
#define MOFF  (CKOFF + LL*4)                   // 102400
#define SMEM_ATTN (MOFF + LL*4)                // 103936

__global__ void __launch_bounds__(256) attn_fused(
    const int* __restrict__ mask, float* __restrict__ attn)
{
    extern __shared__ char smraw[];
    float*  E  = (float*) (smraw + EOFF);   // [32][LLP]
    __half* FQ = (__half*)(smraw + FQOFF);  // [32][FDP]
    __half* FK = (__half*)(smraw + FKOFF);  // [64][FDP]
    __half* Vh = (__half*)(smraw + VHOFF);  // [64][VHS]
    float*  CK = (float*) (smraw + CKOFF);
    int*    M  = (int*)   (smraw + MOFF);

    int tid = threadIdx.x;
    int lane = tid & 31, warp = tid >> 5;
    int wm = (warp & 1) * 16;
    int wn = (warp >> 1) * 16;
    int gr = lane >> 2, tg = lane & 3;
    int bh = blockIdx.y, b = bh >> 3, h = bh & 7;
    int q0 = blockIdx.x * 32;

    for (int j = tid; j < LL; j += 256) { M[j] = mask[b * LL + j]; CK[j] = g_ck[bh * LL + j]; }
    {
        const unsigned* s32 = (const unsigned*)(g_FQ + (size_t)(bh * LL + q0) * FD);
#pragma unroll
        for (int i = 0; i < 16; i++) {
            int idx = tid + i * 256;
            int r = idx >> 7, c2 = idx & 127;
            *(unsigned*)&FQ[r * FDP + c2 * 2] = s32[r * 128 + c2];
        }
    }

    // ---- E phase: register double-buffered FK chunks ----
    const uint4* fksrc = (const uint4*)(g_FK + (size_t)bh * LL * FD);  // chunk c at +c*1024 uint4
    uint4 pfk[8];
#pragma unroll
    for (int i = 0; i < 8; i++) pfk[i] = fksrc[tid + i * 256];

    for (int c = 0; c < 6; c++) {
        __syncthreads();   // prior-chunk MMA reads done (also covers FQ staging on c=0)
#pragma unroll
        for (int i = 0; i < 8; i++) {
            int flat = tid + i * 256;          // 0..2047 uint4
            int r = flat >> 5, c16 = flat & 31;
            *(uint4*)&FK[r * FDP + c16 * 8] = pfk[i];
        }
        __syncthreads();
        if (c < 6 - 1) {
            const uint4* nsrc = fksrc + (c + 1) * 1024;
#pragma unroll
            for (int i = 0; i < 8; i++) pfk[i] = nsrc[tid + i * 256];
        }
        float eacc[2][4];
#pragma unroll
        for (int nt = 0; nt < 2; nt++)
#pragma unroll
            for (int i = 0; i < 4; i++) eacc[nt][i] = 0.f;
#pragma unroll
        for (int ks = 0; ks < 16; ks++) {
            int k0 = ks * 16;
            unsigned a[4], bf[2][2];
            a[0] = *(const unsigned*)&FQ[(wm + gr    ) * FDP + k0 + 2 * tg];
            a[1] = *(const unsigned*)&FQ[(wm + gr + 8) * FDP + k0 + 2 * tg];
            a[2] = *(const unsigned*)&FQ[(wm + gr    ) * FDP + k0 + 2 * tg + 8];
            a[3] = *(const unsigned*)&FQ[(wm + gr + 8) * FDP + k0 + 2 * tg + 8];
#pragma unroll
            for (int nt = 0; nt < 2; nt++) {
                int rn = wn + nt * 8 + gr;
                bf[nt][0] = *(const unsigned*)&FK[rn * FDP + k0 + 2 * tg];
                bf[nt][1] = *(const unsigned*)&FK[rn * FDP + k0 + 2 * tg + 8];
            }
            mma_f16(eacc[0], a, bf[0]);
            mma_f16(eacc[1], a, bf[1]);
        }
#pragma unroll
        for (int nt = 0; nt < 2; nt++) {
            int col = c * 64 + wn + nt * 8 + 2 * tg;
            *(float2*)&E[(wm + gr    ) * LLP + col] = make_float2(eacc[nt][0], eacc[nt][1]);
            *(float2*)&E[(wm + gr + 8) * LLP + col] = make_float2(eacc[nt][2], eacc[nt][3]);
        }
    }
    __syncthreads();

    // ---- softmax ----
    {
        int row = tid >> 3, lx = tid & 7;
        float mx = -3.0e38f;
        for (int i = 0; i < 48; i++) {
            int j = lx + i * 8;
            float e = E[row * LLP + j] + CK[j];
            if (M[j] == 0) e = -1e10f;
            E[row * LLP + j] = e;
            mx = fmaxf(mx, e);
        }
#pragma unroll
        for (int o = 4; o > 0; o >>= 1) mx = fmaxf(mx, __shfl_xor_sync(0xffffffffu, mx, o));
        float sum = 0.f;
        for (int i = 0; i < 48; i++) {
            int j = lx + i * 8;
            float p = __expf(E[row * LLP + j] - mx);
            sum += p;
            E[row * LLP + j] = p;
        }
#pragma unroll
        for (int o = 4; o > 0; o >>= 1) sum += __shfl_xor_sync(0xffffffffu, sum, o);
        float inv = __frcp_rn(sum);
        for (int i = 0; i < 48; i++) E[row * LLP + lx + i * 8] *= inv;
    }
    __syncthreads();

    // ---- prefetch Vh chunk 0 (overlaps attn gmem store) ----
    const uint4* vsrc = (const uint4*)(g_Vh + (size_t)bh * DD * LL);  // row d = 48 uint4; chunk c at +c*8
    int vd = tid >> 3, vc8 = tid & 7;       // per thread: rows vd, vd+32
    uint4 pv[2];
#pragma unroll
    for (int i = 0; i < 2; i++) pv[i] = vsrc[(vd + i * 32) * 48 + vc8];

    // coalesced attn store
    {
        float* dst = attn + (size_t)(bh * LL + q0) * LL;
        for (int idx = tid; idx < 32 * LL; idx += 256) {
            int r = idx / LL, j = idx - r * LL;
            dst[r * LL + j] = E[r * LLP + j];
        }
    }

    // ---- AV phase: register double-buffered Vh chunks ----
    float xacc[2][4];
#pragma unroll
    for (int nt = 0; nt < 2; nt++)
#pragma unroll
        for (int i = 0; i < 4; i++) xacc[nt][i] = 0.f;

    for (int c = 0; c < 6; c++) {
        __syncthreads();   // prior-chunk MMA reads done; FQ region reuse safe (E phase complete)
#pragma unroll
        for (int i = 0; i < 2; i++) {
            int d = vd + i * 32;
            *(uint4*)&Vh[d * VHS + vc8 * 8] = pv[i];
        }
        __syncthreads();
        if (c < 6 - 1) {
#pragma unroll
            for (int i = 0; i < 2; i++) pv[i] = vsrc[(vd + i * 32) * 48 + (c + 1) * 8 + vc8];
        }
#pragma unroll
        for (int ks = 0; ks < 4; ks++) {
            int kg = c * 64 + ks * 16;
            unsigned a[4], bf[2][2];
            float2 p0 = *(const float2*)&E[(wm + gr    ) * LLP + kg + 2 * tg];
            float2 p1 = *(const float2*)&E[(wm + gr + 8) * LLP + kg + 2 * tg];
            float2 p2 = *(const float2*)&E[(wm + gr    ) * LLP + kg + 2 * tg + 8];
            float2 p3 = *(const float2*)&E[(wm + gr + 8) * LLP + kg + 2 * tg + 8];
            a[0] = h2u(__floats2half2_rn(p0.x, p0.y));
            a[1] = h2u(__floats2half2_rn(p1.x, p1.y));
            a[2] = h2u(__floats2half2_rn(p2.x, p2.y));
            a[3] = h2u(__floats2half2_rn(p3.x, p3.y));
            int kl = ks * 16 + 2 * tg;
#pragma unroll
            for (int nt = 0; nt < 2; nt++) {
                int rn = wn + nt * 8 + gr;
                bf[nt][0] = *(const unsigned*)&Vh[rn * VHS + kl];
                bf[nt][1] = *(const unsigned*)&Vh[rn * VHS + kl + 8];
            }
            mma_f16(xacc[0], a, bf[0]);
            mma_f16(xacc[1], a, bf[1]);
        }
    }

    {
        int q = q0 + wm + gr;
#pragma unroll
        for (int nt = 0; nt < 2; nt++) {
            int d = h * DD + wn + nt * 8 + 2 * tg;
            *(float2*)&g_X[(size_t)(b * LL + q    ) * HIDN + d] = make_float2(xacc[nt][0], xacc[nt][1]);
            *(float2*)&g_X[(size_t)(b * LL + q + 8) * HIDN + d] = make_float2(xacc[nt][2], xacc[nt][3]);
        }
    }
}

extern "C" void kernel_launch(void* const* d_in, const int* in_sizes, int n_in,
                              void* d_out, int out_size)
{
    const float* query = (const float*)d_in[0];
    const float* key_  = (const float*)d_in[1];
    const float* value = (const float*)d_in[2];
    const int*   mask  = (const int*)  d_in[3];
    const float* Wq = (const float*)d_in[4];
    const float* bq = (const float*)d_in[5];
    const float* Wk = (const float*)d_in[6];
    const float* bk = (const float*)d_in[7];
    const float* Wv = (const float*)d_in[8];
    const float* bv = (const float*)d_in[9];
    const float* Wo = (const float*)d_in[10];
    const float* bo = (const float*)d_in[11];
    const float* W1 = (const float*)d_in[12];
    const float* b1 = (const float*)d_in[13];
    const float* W2 = (const float*)d_in[14];
    const float* b2 = (const float*)d_in[15];
    const float* vw = (const float*)d_in[16];
    (void)d_in[17];
    (void)in_sizes; (void)n_in;

    float* out = (float*)d_out;

    float *gX, *gA, *gWfq, *gWfk, *gbfq, *gbfk;
    cudaGetSymbolAddress((void**)&gX,   g_X);
    cudaGetSymbolAddress((void**)&gA,   g_attn);
    cudaGetSymbolAddress((void**)&gWfq, g_Wfq);
    cudaGetSymbolAddress((void**)&gWfk, g_Wfk);
    cudaGetSymbolAddress((void**)&gbfq, g_bfq);
    cudaGetSymbolAddress((void**)&gbfk, g_bfk);

    float* attn_dst = (out_size >= X_ELEMS + A_ELEMS) ? (out + X_ELEMS) : gA;

    cudaFuncSetAttribute(attn_fused, cudaFuncAttributeMaxDynamicSharedMemorySize, SMEM_ATTN);

    // 1) fuse W1@Wq and W2@Wk (128 blocks)
    prep_fuse<<<dim3(HH, 2, HIDN / 64), 256>>>(W1, b1, W2, b2, Wq, bq, Wk, bk);

    // 2) projections + featurization — f16 TC BK=64, 288 blocks (BM=64)
    gemm_tc<64><<<dim3(HIDN / 64, MROWS / 64, 3), 256>>>(
        query, gWfq, gbfq, nullptr, 3,
        key_,  gWfk, gbfk, nullptr, 4,
        value, Wv,   bv,   nullptr, 5,
        vw);

    // 3) attention: E-mma + softmax + AV-mma, double-buffered (192 blocks)
    attn_fused<<<dim3(LL / 32, BH), 256, SMEM_ATTN>>>(mask, attn_dst);

    // 4) output projection — f16 TC BK=64, 192 blocks (BM=32)
    gemm_tc<32><<<dim3(HIDN / 64, MROWS / 32, 1), 256>>>(
        gX, Wo, bo, out, 0,
        gX, Wo, bo, out, 0,
        gX, Wo, bo, out, 0,
        vw);
}

// round 16
// speedup vs baseline: 1.4250x; 1.1068x over previous
#include <cuda_runtime.h>
#include <cuda_fp16.h>

#define BB 2
#define LL 384
#define HH 8
#define DD 64
#define HIDN 512
#define BH (BB*HH)          // 16
#define MROWS (BB*LL)       // 768
#define X_ELEMS (MROWS*HIDN)    // 393216
#define A_ELEMS (BH*LL*LL)      // 2359296
#define FD 128              // feature dim (2 segments x 64; x^2 correction dropped)

// -------- scratch (no dynamic allocation allowed) --------
__device__ __half g_FQ[BH*LL*FD];   // [bh][l][128]  q-side features
__device__ __half g_FK[BH*LL*FD];   // [bh][l][128]  k-side features
__device__ __half g_Vh[BH*DD*LL];   // [bh][d][l]    V transposed, half
__device__ float  g_ck[BH*LL];      // per-k energy constant
__device__ float  g_X [X_ELEMS];
__device__ float  g_attn[A_ELEMS];
__device__ float  g_Wfq[HIDN*HIDN];
__device__ float  g_Wfk[HIDN*HIDN];
__device__ float  g_bfq[HIDN];
__device__ float  g_bfk[HIDN];

__device__ __forceinline__ float tanh_ap(float x) {
    float y; asm("tanh.approx.f32 %0, %1;" : "=f"(y) : "f"(x)); return y;
}
__device__ __forceinline__ void mma_f16(float* c, const unsigned* a, const unsigned* b) {
    asm volatile(
        "mma.sync.aligned.m16n8k16.row.col.f32.f16.f16.f32 "
        "{%0,%1,%2,%3}, {%4,%5,%6,%7}, {%8,%9}, {%0,%1,%2,%3};"
        : "+f"(c[0]), "+f"(c[1]), "+f"(c[2]), "+f"(c[3])
        : "r"(a[0]), "r"(a[1]), "r"(a[2]), "r"(a[3]), "r"(b[0]), "r"(b[1]));
}
__device__ __forceinline__ unsigned h2u(__half2 v) { return *(unsigned*)&v; }

// ---------------- prep: fused per-head weights ----------------
__global__ void __launch_bounds__(256) prep_fuse(
    const float* __restrict__ W1, const float* __restrict__ b1,
    const float* __restrict__ W2, const float* __restrict__ b2,
    const float* __restrict__ Wq, const float* __restrict__ bq,
    const float* __restrict__ Wk, const float* __restrict__ bk)
{
    int h   = blockIdx.x;
    int sel = blockIdx.y;
    int c0  = blockIdx.z * 64;
    const float* Wh   = sel ? W2 : W1;
    const float* bh_  = sel ? b2 : b1;
    const float* Wsrc = sel ? Wk : Wq;
    const float* bsrc = sel ? bk : bq;
    float* Wout = sel ? g_Wfk : g_Wfq;
    float* bout = sel ? g_bfk : g_bfq;
    __shared__ float Ws[DD][DD + 1];
    __shared__ float Ts[DD][DD + 1];
    int tid = threadIdx.x;
    for (int t = tid; t < DD * DD; t += 256) {
        Ws[t >> 6][t & 63] = Wh[t];
        Ts[t >> 6][t & 63] = Wsrc[(h * DD + (t >> 6)) * HIDN + c0 + (t & 63)];
    }
    __syncthreads();
    if (blockIdx.z == 0 && tid < DD) {
        float acc = bh_[tid];
        for (int j = 0; j < DD; j++) acc += Ws[tid][j] * bsrc[h * DD + j];
        bout[h * DD + tid] = acc;
    }
    int i = tid & 63;
    int g = tid >> 6;
#pragma unroll
    for (int cc = 0; cc < 16; cc++) {
        int c = g * 16 + cc;
        float acc = 0.f;
#pragma unroll 8
        for (int j = 0; j < DD; j++) acc = fmaf(Ws[i][j], Ts[j][c], acc);
        Wout[(h * DD + i) * HIDN + c0 + c] = acc;
    }
}

// ---------------- f16 TC GEMM: BK=64, m16n8k16, f32 accum ----------------
template<int BM>
__global__ void __launch_bounds__(256) gemm_tc(
    const float* __restrict__ X0, const float* __restrict__ Wm0, const float* __restrict__ B0, float* __restrict__ O0, int md0,
    const float* __restrict__ X1, const float* __restrict__ Wm1, const float* __restrict__ B1, float* __restrict__ O1, int md1,
    const float* __restrict__ X2, const float* __restrict__ Wm2, const float* __restrict__ B2, float* __restrict__ O2, int md2,
    const float* __restrict__ vw)
{
    const int BK = 64;
    const int NIT = HIDN / BK;        // 8
    const int NT = (BM == 64) ? 4 : 2;
    const int NLX = BM / 16;
    int z = blockIdx.z;
    const float* X  = z == 0 ? X0  : (z == 1 ? X1  : X2);
    const float* W  = z == 0 ? Wm0 : (z == 1 ? Wm1 : Wm2);
    const float* Bi = z == 0 ? B0  : (z == 1 ? B1  : B2);
    float*       O  = z == 0 ? O0  : (z == 1 ? O1  : O2);
    int        mode = z == 0 ? md0 : (z == 1 ? md1 : md2);

    __shared__ union {
        struct { unsigned X[BM * 36]; unsigned W[64 * 36]; } st;
        float out[BM * 68];
    } sm;

    int tid = threadIdx.x;
    int lane = tid & 31;
    int warp = tid >> 5;
    int warp_m = (BM == 64) ? (warp & 3) * 16 : (warp & 1) * 16;
    int warp_n = (BM == 64) ? (warp >> 2) * 32 : (warp >> 1) * 16;
    int gr = lane >> 2;
    int tg = lane & 3;
    int m0 = blockIdx.y * BM, n0 = blockIdx.x * 64;

    float acc[NT][4];
#pragma unroll
    for (int nt = 0; nt < NT; nt++)
#pragma unroll
        for (int i = 0; i < 4; i++) acc[nt][i] = 0.f;

    float4 px[NLX], pw[4];
#pragma unroll
    for (int i = 0; i < NLX; i++) {
        int idx = tid + i * 256;
        int r = idx >> 4, c4 = idx & 15;
        px[i] = *(const float4*)&X[(m0 + r) * HIDN + c4 * 4];
    }
#pragma unroll
    for (int i = 0; i < 4; i++) {
        int idx = tid + i * 256;
        int r = idx >> 4, c4 = idx & 15;
        pw[i] = *(const float4*)&W[(n0 + r) * HIDN + c4 * 4];
    }

    for (int it = 0; it < NIT; it++) {
#pragma unroll
        for (int i = 0; i < NLX; i++) {
            int idx = tid + i * 256;
            int r = idx >> 4, c4 = idx & 15;
            uint2 u;
            u.x = h2u(__floats2half2_rn(px[i].x, px[i].y));
            u.y = h2u(__floats2half2_rn(px[i].z, px[i].w));
            *(uint2*)&sm.st.X[r * 36 + c4 * 2] = u;
        }
#pragma unroll
        for (int i = 0; i < 4; i++) {
            int idx = tid + i * 256;
            int r = idx >> 4, c4 = idx & 15;
            uint2 u;
            u.x = h2u(__floats2half2_rn(pw[i].x, pw[i].y));
            u.y = h2u(__floats2half2_rn(pw[i].z, pw[i].w));
            *(uint2*)&sm.st.W[r * 36 + c4 * 2] = u;
        }
        __syncthreads();
        if (it + 1 < NIT) {
            int kk = (it + 1) * BK;
#pragma unroll
            for (int i = 0; i < NLX; i++) {
                int idx = tid + i * 256;
                int r = idx >> 4, c4 = idx & 15;
                px[i] = *(const float4*)&X[(m0 + r) * HIDN + kk + c4 * 4];
            }
#pragma unroll
            for (int i = 0; i < 4; i++) {
                int idx = tid + i * 256;
                int r = idx >> 4, c4 = idx & 15;
                pw[i] = *(const float4*)&W[(n0 + r) * HIDN + kk + c4 * 4];
            }
        }
#pragma unroll
        for (int s = 0; s < 4; s++) {
            int kb = s * 8;
            unsigned a[4], b[NT][2];
            a[0] = sm.st.X[(warp_m + gr    ) * 36 + kb + tg];
            a[1] = sm.st.X[(warp_m + gr + 8) * 36 + kb + tg];
            a[2] = sm.st.X[(warp_m + gr    ) * 36 + kb + 4 + tg];
            a[3] = sm.st.X[(warp_m + gr + 8) * 36 + kb + 4 + tg];
#pragma unroll
            for (int nt = 0; nt < NT; nt++) {
                int rn = warp_n + nt * 8 + gr;
                b[nt][0] = sm.st.W[rn * 36 + kb + tg];
                b[nt][1] = sm.st.W[rn * 36 + kb + 4 + tg];
            }
#pragma unroll
            for (int nt = 0; nt < NT; nt++)
                mma_f16(acc[nt], a, b[nt]);
        }
        __syncthreads();
    }

#pragma unroll
    for (int nt = 0; nt < NT; nt++) {
        int col = warp_n + nt * 8 + 2 * tg;
        sm.out[(warp_m + gr    ) * 68 + col    ] = acc[nt][0];
        sm.out[(warp_m + gr    ) * 68 + col + 1] = acc[nt][1];
        sm.out[(warp_m + gr + 8) * 68 + col    ] = acc[nt][2];
        sm.out[(warp_m + gr + 8) * 68 + col + 1] = acc[nt][3];
    }
    __syncthreads();

    int b_ = m0 / LL, l0 = m0 - b_ * LL;
    int h = n0 >> 6;
    int bh = b_ * HH + h;

    if (mode == 0) {
#pragma unroll
        for (int i = 0; i < BM / 16; i++) {
            int idx = tid + i * 256;
            int r = idx >> 4, c4 = idx & 15;
            float4 v = *(float4*)&sm.out[r * 68 + c4 * 4];
            float4 b4 = *(const float4*)&Bi[n0 + c4 * 4];
            v.x += b4.x; v.y += b4.y; v.z += b4.z; v.w += b4.w;
            *(float4*)&O[(m0 + r) * HIDN + n0 + c4 * 4] = v;
        }
    } else if (mode == 3 || mode == 4) {
        __half* Fdst = (mode == 3 ? g_FQ : g_FK) + (size_t)(bh * LL + l0) * FD;
#pragma unroll
        for (int i = 0; i < BM / 16; i++) {
            int idx = tid + i * 256;
            int r = idx >> 4, c4 = idx & 15;
            int d0 = c4 * 4;
            float4 v = *(float4*)&sm.out[r * 68 + d0];
            float4 b4 = *(const float4*)&Bi[n0 + d0];
            float t0 = tanh_ap(v.x + b4.x), t1 = tanh_ap(v.y + b4.y);
            float t2 = tanh_ap(v.z + b4.z), t3 = tanh_ap(v.w + b4.w);
            float w0 = __ldg(&vw[d0]), w1 = __ldg(&vw[d0 + 1]);
            float w2 = __ldg(&vw[d0 + 2]), w3 = __ldg(&vw[d0 + 3]);
            __half* row = Fdst + (size_t)r * FD;
            if (mode == 3) {
                // FQ = [ta^2, vw*ta]
                *(__half2*)&row[0*64 + d0    ] = __floats2half2_rn(t0*t0, t1*t1);
                *(__half2*)&row[0*64 + d0 + 2] = __floats2half2_rn(t2*t2, t3*t3);
                *(__half2*)&row[1*64 + d0    ] = __floats2half2_rn(w0*t0, w1*t1);
                *(__half2*)&row[1*64 + d0 + 2] = __floats2half2_rn(w2*t2, w3*t3);
            } else {
                // FK = [-vw*tb, -tb^2]
                *(__half2*)&row[0*64 + d0    ] = __floats2half2_rn(-w0*t0, -w1*t1);
                *(__half2*)&row[0*64 + d0 + 2] = __floats2half2_rn(-w2*t2, -w3*t3);
                *(__half2*)&row[1*64 + d0    ] = __floats2half2_rn(-t0*t0, -t1*t1);
                *(__half2*)&row[1*64 + d0 + 2] = __floats2half2_rn(-t2*t2, -t3*t3);
                float cp = w0*t0 + w1*t1 + w2*t2 + w3*t3;
#pragma unroll
                for (int o = 1; o < 16; o <<= 1) cp += __shfl_xor_sync(0xffffffffu, cp, o);
                if ((tid & 15) == 0) g_ck[bh * LL + l0 + r] = cp;
            }
        }
    } else {
        __half* base = g_Vh + (size_t)bh * DD * LL;
#pragma unroll
        for (int i = 0; i < BM / 16; i++) {
            int idx = tid + i * 256;
            int d = idx >> 4, l4 = idx & 15;
            float bd = __ldg(&Bi[n0 + d]);
            float v0 = sm.out[(l4 * 4 + 0) * 68 + d] + bd;
            float v1 = sm.out[(l4 * 4 + 1) * 68 + d] + bd;
            float v2 = sm.out[(l4 * 4 + 2) * 68 + d] + bd;
            float v3 = sm.out[(l4 * 4 + 3) * 68 + d] + bd;
            *(__half2*)&base[d * LL + l0 + l4 * 4    ] = __floats2half2_rn(v0, v1);
            *(__half2*)&base[d * LL + l0 + l4 * 4 + 2] = __floats2half2_rn(v2, v3);
        }
    }
}

// ---------------- attention: E = FQ@FK^T + ck -> softmax -> X = P@V (f16 MMA) ----
// FD=128; register double-buffered FK / Vh chunk loads.
#define LLP 392
#define FDP 136
#define VHS 72
#define EOFF  0
#define FQOFF (32*LLP*4)                       // 50176
#define FKOFF (FQOFF + 32*FDP*2)               // 58880
#define VHOFF FKOFF                            // Vh overlays FK (used after E phase)
#define CKOFF (FKOFF + 64*FDP*2)               // 76288
#define MOFF  (CKOFF + LL*4)                   // 77824
#define SMEM_ATTN (MOFF + LL*4)                // 79360

__global__ void __launch_bounds__(256) attn_fused(
    const int* __restrict__ mask, float* __restrict__ attn)
{
    extern __shared__ char smraw[];
    float*  E  = (float*) (smraw + EOFF);   // [32][LLP]
    __half* FQ = (__half*)(smraw + FQOFF);  // [32][FDP]
    __half* FK = (__half*)(smraw + FKOFF);  // [64][FDP]
    __half* Vh = (__half*)(smraw + VHOFF);  // [64][VHS]
    float*  CK = (float*) (smraw + CKOFF);
    int*    M  = (int*)   (smraw + MOFF);

    int tid = threadIdx.x;
    int lane = tid & 31, warp = tid >> 5;
    int wm = (warp & 1) * 16;
    int wn = (warp >> 1) * 16;
    int gr = lane >> 2, tg = lane & 3;
    int bh = blockIdx.y, b = bh >> 3, h = bh & 7;
    int q0 = blockIdx.x * 32;

    for (int j = tid; j < LL; j += 256) { M[j] = mask[b * LL + j]; CK[j] = g_ck[bh * LL + j]; }
    {
        const unsigned* s32 = (const unsigned*)(g_FQ + (size_t)(bh * LL + q0) * FD);
#pragma unroll
        for (int i = 0; i < 8; i++) {
            int idx = tid + i * 256;            // 0..2047 words (32 rows x 64 words)
            int r = idx >> 6, c2 = idx & 63;
            *(unsigned*)&FQ[r * FDP + c2 * 2] = s32[r * 64 + c2];
        }
    }

    // ---- E phase: register double-buffered FK chunks (chunk = 64 rows x 128 halves = 1024 uint4) ----
    const uint4* fksrc = (const uint4*)(g_FK + (size_t)bh * LL * FD);
    uint4 pfk[4];
#pragma unroll
    for (int i = 0; i < 4; i++) pfk[i] = fksrc[tid + i * 256];

    for (int c = 0; c < 6; c++) {
        __syncthreads();   // prior-chunk MMA reads done (also covers FQ staging on c=0)
#pragma unroll
        for (int i = 0; i < 4; i++) {
            int flat = tid + i * 256;          // 0..1023 uint4
            int r = flat >> 4, c16 = flat & 15;
            *(uint4*)&FK[r * FDP + c16 * 8] = pfk[i];
        }
        __syncthreads();
        if (c < 6 - 1) {
            const uint4* nsrc = fksrc + (c + 1) * 1024;
#pragma unroll
            for (int i = 0; i < 4; i++) pfk[i] = nsrc[tid + i * 256];
        }
        float eacc[2][4];
#pragma unroll
        for (int nt = 0; nt < 2; nt++)
#pragma unroll
            for (int i = 0; i < 4; i++) eacc[nt][i] = 0.f;
#pragma unroll
        for (int ks = 0; ks < FD / 16; ks++) {
            int k0 = ks * 16;
            unsigned a[4], bf[2][2];
            a[0] = *(const unsigned*)&FQ[(wm + gr    ) * FDP + k0 + 2 * tg];
            a[1] = *(const unsigned*)&FQ[(wm + gr + 8) * FDP + k0 + 2 * tg];
            a[2] = *(const unsigned*)&FQ[(wm + gr    ) * FDP + k0 + 2 * tg + 8];
            a[3] = *(const unsigned*)&FQ[(wm + gr + 8) * FDP + k0 + 2 * tg + 8];
#pragma unroll
            for (int nt = 0; nt < 2; nt++) {
                int rn = wn + nt * 8 + gr;
                bf[nt][0] = *(const unsigned*)&FK[rn * FDP + k0 + 2 * tg];
                bf[nt][1] = *(const unsigned*)&FK[rn * FDP + k0 + 2 * tg + 8];
            }
            mma_f16(eacc[0], a, bf[0]);
            mma_f16(eacc[1], a, bf[1]);
        }
#pragma unroll
        for (int nt = 0; nt < 2; nt++) {
            int col = c * 64 + wn + nt * 8 + 2 * tg;
            *(float2*)&E[(wm + gr    ) * LLP + col] = make_float2(eacc[nt][0], eacc[nt][1]);
            *(float2*)&E[(wm + gr + 8) * LLP + col] = make_float2(eacc[nt][2], eacc[nt][3]);
        }
    }
    __syncthreads();

    // ---- softmax ----
    {
        int row = tid >> 3, lx = tid & 7;
        float mx = -3.0e38f;
        for (int i = 0; i < 48; i++) {
            int j = lx + i * 8;
            float e = E[row * LLP + j] + CK[j];
            if (M[j] == 0) e = -1e10f;
            E[row * LLP + j] = e;
            mx = fmaxf(mx, e);
        }
#pragma unroll
        for (int o = 4; o > 0; o >>= 1) mx = fmaxf(mx, __shfl_xor_sync(0xffffffffu, mx, o));
        float sum = 0.f;
        for (int i = 0; i < 48; i++) {
            int j = lx + i * 8;
            float p = __expf(E[row * LLP + j] - mx);
            sum += p;
            E[row * LLP + j] = p;
        }
#pragma unroll
        for (int o = 4; o > 0; o >>= 1) sum += __shfl_xor_sync(0xffffffffu, sum, o);
        float inv = __frcp_rn(sum);
        for (int i = 0; i < 48; i++) E[row * LLP + lx + i * 8] *= inv;
    }
    __syncthreads();

    // ---- prefetch Vh chunk 0 (overlaps attn gmem store) ----
    const uint4* vsrc = (const uint4*)(g_Vh + (size_t)bh * DD * LL);  // row d = 48 uint4; chunk c at +c*8
    int vd = tid >> 3, vc8 = tid & 7;
    uint4 pv[2];
#pragma unroll
    for (int i = 0; i < 2; i++) pv[i] = vsrc[(vd + i * 32) * 48 + vc8];

    {
        float* dst = attn + (size_t)(bh * LL + q0) * LL;
        for (int idx = tid; idx < 32 * LL; idx += 256) {
            int r = idx / LL, j = idx - r * LL;
            dst[r * LL + j] = E[r * LLP + j];
        }
    }

    // ---- AV phase: register double-buffered Vh chunks ----
    float xacc[2][4];
#pragma unroll
    for (int nt = 0; nt < 2; nt++)
#pragma unroll
        for (int i = 0; i < 4; i++) xacc[nt][i] = 0.f;

    for (int c = 0; c < 6; c++) {
        __syncthreads();
#pragma unroll
        for (int i = 0; i < 2; i++) {
            int d = vd + i * 32;
            *(uint4*)&Vh[d * VHS + vc8 * 8] = pv[i];
        }
        __syncthreads();
        if (c < 6 - 1) {
#pragma unroll
            for (int i = 0; i < 2; i++) pv[i] = vsrc[(vd + i * 32) * 48 + (c + 1) * 8 + vc8];
        }
#pragma unroll
        for (int ks = 0; ks < 4; ks++) {
            int kg = c * 64 + ks * 16;
            unsigned a[4], bf[2][2];
            float2 p0 = *(const float2*)&E[(wm + gr    ) * LLP + kg + 2 * tg];
            float2 p1 = *(const float2*)&E[(wm + gr + 8) * LLP + kg + 2 * tg];
            float2 p2 = *(const float2*)&E[(wm + gr    ) * LLP + kg + 2 * tg + 8];
            float2 p3 = *(const float2*)&E[(wm + gr + 8) * LLP + kg + 2 * tg + 8];
            a[0] = h2u(__floats2half2_rn(p0.x, p0.y));
            a[1] = h2u(__floats2half2_rn(p1.x, p1.y));
            a[2] = h2u(__floats2half2_rn(p2.x, p2.y));
            a[3] = h2u(__floats2half2_rn(p3.x, p3.y));
            int kl = ks * 16 + 2 * tg;
#pragma unroll
            for (int nt = 0; nt < 2; nt++) {
                int rn = wn + nt * 8 + gr;
                bf[nt][0] = *(const unsigned*)&Vh[rn * VHS + kl];
                bf[nt][1] = *(const unsigned*)&Vh[rn * VHS + kl + 8];
            }
            mma_f16(xacc[0], a, bf[0]);
            mma_f16(xacc[1], a, bf[1]);
        }
    }

    {
        int q = q0 + wm + gr;
#pragma unroll
        for (int nt = 0; nt < 2; nt++) {
            int d = h * DD + wn + nt * 8 + 2 * tg;
            *(float2*)&g_X[(size_t)(b * LL + q    ) * HIDN + d] = make_float2(xacc[nt][0], xacc[nt][1]);
            *(float2*)&g_X[(size_t)(b * LL + q + 8) * HIDN + d] = make_float2(xacc[nt][2], xacc[nt][3]);
        }
    }
}

extern "C" void kernel_launch(void* const* d_in, const int* in_sizes, int n_in,
                              void* d_out, int out_size)
{
    const float* query = (const float*)d_in[0];
    const float* key_  = (const float*)d_in[1];
    const float* value = (const float*)d_in[2];
    const int*   mask  = (const int*)  d_in[3];
    const float* Wq = (const float*)d_in[4];
    const float* bq = (const float*)d_in[5];
    const float* Wk = (const float*)d_in[6];
    const float* bk = (const float*)d_in[7];
    const float* Wv = (const float*)d_in[8];
    const float* bv = (const float*)d_in[9];
    const float* Wo = (const float*)d_in[10];
    const float* bo = (const float*)d_in[11];
    const float* W1 = (const float*)d_in[12];
    const float* b1 = (const float*)d_in[13];
    const float* W2 = (const float*)d_in[14];
    const float* b2 = (const float*)d_in[15];
    const float* vw = (const float*)d_in[16];
    (void)d_in[17];
    (void)in_sizes; (void)n_in;

    float* out = (float*)d_out;

    float *gX, *gA, *gWfq, *gWfk, *gbfq, *gbfk;
    cudaGetSymbolAddress((void**)&gX,   g_X);
    cudaGetSymbolAddress((void**)&gA,   g_attn);
    cudaGetSymbolAddress((void**)&gWfq, g_Wfq);
    cudaGetSymbolAddress((void**)&gWfk, g_Wfk);
    cudaGetSymbolAddress((void**)&gbfq, g_bfq);
    cudaGetSymbolAddress((void**)&gbfk, g_bfk);

    float* attn_dst = (out_size >= X_ELEMS + A_ELEMS) ? (out + X_ELEMS) : gA;

    cudaFuncSetAttribute(attn_fused, cudaFuncAttributeMaxDynamicSharedMemorySize, SMEM_ATTN);

    // 1) fuse W1@Wq and W2@Wk (128 blocks)
    prep_fuse<<<dim3(HH, 2, HIDN / 64), 256>>>(W1, b1, W2, b2, Wq, bq, Wk, bk);

    // 2) projections + featurization — f16 TC BK=64, 288 blocks (BM=64)
    gemm_tc<64><<<dim3(HIDN / 64, MROWS / 64, 3), 256>>>(
        query, gWfq, gbfq, nullptr, 3,
        key_,  gWfk, gbfk, nullptr, 4,
        value, Wv,   bv,   nullptr, 5,
        vw);

    // 3) attention: E-mma + softmax + AV-mma, double-buffered, FD=128 (192 blocks)
    attn_fused<<<dim3(LL / 32, BH), 256, SMEM_ATTN>>>(mask, attn_dst);

    // 4) output projection — f16 TC BK=64, 192 blocks (BM=32)
    gemm_tc<32><<<dim3(HIDN / 64, MROWS / 32, 1), 256>>>(
        gX, Wo, bo, out, 0,
        gX, Wo, bo, out, 0,
        gX, Wo, bo, out, 0,
        vw);
}